// round 1
// baseline (speedup 1.0000x reference)
#include <cuda_runtime.h>
#include <math.h>

// Problem dims
#define Bb 4
#define Ss 2048
#define Ee 1024
#define Hh 16
#define Dd 64
#define Ff 4096
constexpr int BS = Bb * Ss;   // 8192 tokens
constexpr int BH = Bb * Hh;   // 64 (batch*heads)

// ---------------- scratch (device globals; no allocation allowed) -----------
__device__ float g_x [BS * Ee];            // embeddings            32 MB
__device__ float g_q [BS * Ee];            // Q                     32 MB
__device__ float g_k [BS * Ee];            // K                     32 MB
__device__ float g_v [BS * Ee];            // V                     32 MB
__device__ float g_sc[(size_t)BH * Ss * Ss]; // scores/probs        1 GiB
__device__ float g_at[BS * Ee];            // attention out         32 MB
__device__ float g_wo[BS * Ee];            // ctx @ Wo              32 MB
__device__ float g_h [BS * Ee];            // post-LN               32 MB
__device__ float g_f1[(size_t)BS * Ff];    // gelu(h@W1)           128 MB
__device__ float g_f2[BS * Ee];            // ff2                   32 MB
__device__ float g_pt[64 * Bb * Ee];       // partial col sums       1 MB

// ---------------- embedding gather ----------------
__global__ void k_embed(const int* __restrict__ ids,
                        const float* __restrict__ emb,
                        float* __restrict__ x) {
    int t = blockIdx.x;
    int id = ids[t];
    const float4* src = (const float4*)(emb + (size_t)id * Ee);
    float4* dst = (float4*)(x + (size_t)t * Ee);
    dst[threadIdx.x] = src[threadIdx.x];   // 256 thr * float4 = 1024 floats
}

// ---------------- generic SGEMM: C[M,N] = A[M,K] @ B[K,N] + bias, opt GELU --
// BM=128 BN=128 BK=16, 256 threads, 8x8 per thread.
template <int EPI>  // 0 = bias only, 1 = bias + exact gelu
__global__ void k_sgemm(const float* __restrict__ A,
                        const float* __restrict__ Bm,
                        const float* __restrict__ bias,
                        float* __restrict__ C,
                        int M, int N, int K) {
    __shared__ float As[16][128];
    __shared__ float Bs[16][128];
    int tid = threadIdx.x;
    int tx = tid & 15, ty = tid >> 4;
    const float* Ap = A + (size_t)blockIdx.y * 128 * K;
    const float* Bp = Bm + (size_t)blockIdx.x * 128;
    float acc[8][8];
#pragma unroll
    for (int i = 0; i < 8; i++)
#pragma unroll
        for (int j = 0; j < 8; j++) acc[i][j] = 0.f;

    for (int k0 = 0; k0 < K; k0 += 16) {
#pragma unroll
        for (int l = 0; l < 2; l++) {            // A tile 128x16 = 512 float4
            int i = tid + l * 256;
            int r = i >> 2, c4 = (i & 3) * 4;
            float4 va = *(const float4*)(Ap + (size_t)r * K + k0 + c4);
            As[c4 + 0][r] = va.x; As[c4 + 1][r] = va.y;
            As[c4 + 2][r] = va.z; As[c4 + 3][r] = va.w;
        }
#pragma unroll
        for (int l = 0; l < 2; l++) {            // B tile 16x128 = 512 float4
            int i = tid + l * 256;
            int r = i >> 5, c4 = (i & 31) * 4;
            *(float4*)&Bs[r][c4] = *(const float4*)(Bp + (size_t)(k0 + r) * N + c4);
        }
        __syncthreads();
#pragma unroll
        for (int k = 0; k < 16; k++) {
            float a[8], b[8];
            *(float4*)&a[0] = *(float4*)&As[k][ty * 8];
            *(float4*)&a[4] = *(float4*)&As[k][ty * 8 + 4];
            *(float4*)&b[0] = *(float4*)&Bs[k][tx * 8];
            *(float4*)&b[4] = *(float4*)&Bs[k][tx * 8 + 4];
#pragma unroll
            for (int i = 0; i < 8; i++)
#pragma unroll
                for (int j = 0; j < 8; j++) acc[i][j] += a[i] * b[j];
        }
        __syncthreads();
    }

    int row0 = blockIdx.y * 128 + ty * 8;
    int col0 = blockIdx.x * 128 + tx * 8;
#pragma unroll
    for (int i = 0; i < 8; i++) {
#pragma unroll
        for (int j = 0; j < 8; j++) {
            float t = acc[i][j] + bias[col0 + j];
            if (EPI == 1)
                t = 0.5f * t * (1.0f + erff(t * 0.70710678118654752f));
            C[(size_t)(row0 + i) * N + col0 + j] = t;
        }
    }
}

// ---------------- attention scores: S[q,k] = Q·K^T / 8 ----------------
__global__ void k_scores(const float* __restrict__ q,
                         const float* __restrict__ k,
                         float* __restrict__ sc) {
    int bh = blockIdx.z;
    int b = bh / Hh, h = bh % Hh;
    int q0 = blockIdx.y * 64, k0 = blockIdx.x * 64;
    __shared__ float Qs[64][65];
    __shared__ float Ks[64][65];
    int tid = threadIdx.x;
    const float* qb = q + ((size_t)(b * Ss + q0)) * Ee + h * Dd;
    const float* kb = k + ((size_t)(b * Ss + k0)) * Ee + h * Dd;
#pragma unroll
    for (int l = 0; l < 4; l++) {
        int i = tid + l * 256;
        int r = i >> 4, c4 = (i & 15) * 4;
        float4 vq = *(const float4*)(qb + (size_t)r * Ee + c4);
        Qs[r][c4 + 0] = vq.x; Qs[r][c4 + 1] = vq.y;
        Qs[r][c4 + 2] = vq.z; Qs[r][c4 + 3] = vq.w;
        float4 vk = *(const float4*)(kb + (size_t)r * Ee + c4);
        Ks[r][c4 + 0] = vk.x; Ks[r][c4 + 1] = vk.y;
        Ks[r][c4 + 2] = vk.z; Ks[r][c4 + 3] = vk.w;
    }
    __syncthreads();
    int tx = tid & 15, ty = tid >> 4;
    float acc[4][4];
#pragma unroll
    for (int i = 0; i < 4; i++)
#pragma unroll
        for (int j = 0; j < 4; j++) acc[i][j] = 0.f;
#pragma unroll 8
    for (int d = 0; d < 64; d++) {
        float a[4], bb[4];
#pragma unroll
        for (int i = 0; i < 4; i++) a[i] = Qs[ty * 4 + i][d];
#pragma unroll
        for (int j = 0; j < 4; j++) bb[j] = Ks[tx * 4 + j][d];
#pragma unroll
        for (int i = 0; i < 4; i++)
#pragma unroll
            for (int j = 0; j < 4; j++) acc[i][j] += a[i] * bb[j];
    }
    const float scale = 0.125f;  // 1/sqrt(64)
#pragma unroll
    for (int i = 0; i < 4; i++)
#pragma unroll
        for (int j = 0; j < 4; j++)
            sc[((size_t)bh * Ss + q0 + ty * 4 + i) * Ss + k0 + tx * 4 + j] =
                acc[i][j] * scale;
}

// ---------------- row softmax (with mask) ----------------
__global__ void k_softmax(float* __restrict__ sc, const int* __restrict__ mask) {
    __shared__ float red[256];
    size_t base = (size_t)blockIdx.x * Ss;
    int b = blockIdx.x / (Hh * Ss);
    const int* mrow = mask + b * Ss;
    int tid = threadIdx.x;
    float vals[8];
    float mx = -INFINITY;
#pragma unroll
    for (int i = 0; i < 8; i++) {
        int c = i * 256 + tid;
        float v = sc[base + c];
        if (mrow[c] == 0) v = -INFINITY;
        vals[i] = v;
        mx = fmaxf(mx, v);
    }
    red[tid] = mx; __syncthreads();
    for (int s = 128; s > 0; s >>= 1) {
        if (tid < s) red[tid] = fmaxf(red[tid], red[tid + s]);
        __syncthreads();
    }
    mx = red[0]; __syncthreads();
    float sum = 0.f;
#pragma unroll
    for (int i = 0; i < 8; i++) {
        float e = __expf(vals[i] - mx);
        vals[i] = e;
        sum += e;
    }
    red[tid] = sum; __syncthreads();
    for (int s = 128; s > 0; s >>= 1) {
        if (tid < s) red[tid] += red[tid + s];
        __syncthreads();
    }
    float inv = 1.0f / red[0];
#pragma unroll
    for (int i = 0; i < 8; i++) {
        int c = i * 256 + tid;
        sc[base + c] = vals[i] * inv;
    }
}

// ---------------- ctx = P @ V ----------------
__global__ void k_ctx(const float* __restrict__ sc,
                      const float* __restrict__ v,
                      float* __restrict__ o) {
    int bh = blockIdx.y;
    int b = bh / Hh, h = bh % Hh;
    int q0 = blockIdx.x * 64;
    __shared__ float Ps[64][65];
    __shared__ float Vs[64][64];
    int tid = threadIdx.x;
    int tx = tid & 15, ty = tid >> 4;
    float acc[4][4];
#pragma unroll
    for (int i = 0; i < 4; i++)
#pragma unroll
        for (int j = 0; j < 4; j++) acc[i][j] = 0.f;

    for (int kt = 0; kt < Ss; kt += 64) {
#pragma unroll
        for (int l = 0; l < 4; l++) {
            int i = tid + l * 256;
            int r = i >> 4, c4 = (i & 15) * 4;
            float4 vp = *(const float4*)(sc + ((size_t)bh * Ss + q0 + r) * Ss + kt + c4);
            Ps[r][c4 + 0] = vp.x; Ps[r][c4 + 1] = vp.y;
            Ps[r][c4 + 2] = vp.z; Ps[r][c4 + 3] = vp.w;
            float4 vv = *(const float4*)(v + ((size_t)(b * Ss + kt + r)) * Ee + h * Dd + c4);
            *(float4*)&Vs[r][c4] = vv;
        }
        __syncthreads();
#pragma unroll 8
        for (int kk = 0; kk < 64; kk++) {
            float a[4], bb[4];
#pragma unroll
            for (int i = 0; i < 4; i++) a[i] = Ps[ty * 4 + i][kk];
#pragma unroll
            for (int j = 0; j < 4; j++) bb[j] = Vs[kk][tx * 4 + j];
#pragma unroll
            for (int i = 0; i < 4; i++)
#pragma unroll
                for (int j = 0; j < 4; j++) acc[i][j] += a[i] * bb[j];
        }
        __syncthreads();
    }
#pragma unroll
    for (int i = 0; i < 4; i++)
#pragma unroll
        for (int j = 0; j < 4; j++)
            o[((size_t)(b * Ss + q0 + ty * 4 + i)) * Ee + h * Dd + tx * 4 + j] =
                acc[i][j];
}

// ---------------- residual + layernorm ----------------
__global__ void k_ln(const float* __restrict__ wo_out,
                     const float* __restrict__ x,
                     const float* __restrict__ g,
                     const float* __restrict__ be,
                     float* __restrict__ out) {
    __shared__ float red[256];
    __shared__ float s_mu, s_rstd;
    int t = blockIdx.x;
    int tid = threadIdx.x;
    const float* pa = wo_out + (size_t)t * Ee;
    const float* px = x + (size_t)t * Ee;
    float loc[4];
    float sum = 0.f;
#pragma unroll
    for (int i = 0; i < 4; i++) {
        int idx = i * 256 + tid;
        float vv = pa[idx] + px[idx];
        loc[i] = vv;
        sum += vv;
    }
    red[tid] = sum; __syncthreads();
    for (int s = 128; s > 0; s >>= 1) {
        if (tid < s) red[tid] += red[tid + s];
        __syncthreads();
    }
    if (tid == 0) s_mu = red[0] * (1.0f / Ee);
    __syncthreads();
    float mu = s_mu;
    float vs = 0.f;
#pragma unroll
    for (int i = 0; i < 4; i++) {
        float d = loc[i] - mu;
        vs += d * d;
    }
    red[tid] = vs; __syncthreads();
    for (int s = 128; s > 0; s >>= 1) {
        if (tid < s) red[tid] += red[tid + s];
        __syncthreads();
    }
    if (tid == 0) s_rstd = rsqrtf(red[0] * (1.0f / Ee) + 1e-5f);
    __syncthreads();
    float rstd = s_rstd;
#pragma unroll
    for (int i = 0; i < 4; i++) {
        int idx = i * 256 + tid;
        out[(size_t)t * Ee + idx] = (loc[i] - mu) * rstd * g[idx] + be[idx];
    }
}

// ---------------- partial column sums of ff2 ----------------
__global__ void k_pmean(const float* __restrict__ f2, float* __restrict__ part) {
    int e = blockIdx.x * 256 + threadIdx.x;
    int b = blockIdx.y;
    int p = blockIdx.z;  // 64 splits x 32 rows
    float s = 0.f;
    int s0 = p * 32;
    for (int i = 0; i < 32; i++)
        s += f2[((size_t)(b * Ss + s0 + i)) * Ee + e];
    part[((size_t)p * Bb + b) * Ee + e] = s;
}

// ---------------- final: out[b][j] = (sum_s ff)/S @ Wp + bp ----------------
__global__ void k_final(const float* __restrict__ part,
                        const float* __restrict__ Wp,
                        const float* __restrict__ bp,
                        float* __restrict__ out) {
    int w = threadIdx.x >> 5;
    int lane = threadIdx.x & 31;
    if (w >= 12) return;
    int b = w / 3, j = w % 3;
    float acc = 0.f;
    for (int e = lane; e < Ee; e += 32) {
        float s = 0.f;
#pragma unroll
        for (int p = 0; p < 64; p++)
            s += part[((size_t)p * Bb + b) * Ee + e];
        acc += s * Wp[e * 3 + j];
    }
#pragma unroll
    for (int o = 16; o > 0; o >>= 1)
        acc += __shfl_down_sync(0xffffffff, acc, o);
    if (lane == 0) out[b * 3 + j] = acc * (1.0f / Ss) + bp[j];
}

// ---------------- launch ----------------
extern "C" void kernel_launch(void* const* d_in, const int* in_sizes, int n_in,
                              void* d_out, int out_size) {
    const int*   ids  = (const int*)d_in[0];
    const int*   mask = (const int*)d_in[1];
    const float* emb  = (const float*)d_in[2];
    const float* Wq = (const float*)d_in[3],  *bq = (const float*)d_in[4];
    const float* Wk = (const float*)d_in[5],  *bk = (const float*)d_in[6];
    const float* Wv = (const float*)d_in[7],  *bv = (const float*)d_in[8];
    const float* Wo = (const float*)d_in[9],  *bo = (const float*)d_in[10];
    const float* lg = (const float*)d_in[11], *lb = (const float*)d_in[12];
    const float* W1 = (const float*)d_in[13], *b1 = (const float*)d_in[14];
    const float* W2 = (const float*)d_in[15], *b2 = (const float*)d_in[16];
    const float* Wp = (const float*)d_in[17], *bp = (const float*)d_in[18];

    float *x, *q, *k, *v, *sc, *at, *wo, *h, *f1, *f2, *pt;
    cudaGetSymbolAddress((void**)&x,  g_x);
    cudaGetSymbolAddress((void**)&q,  g_q);
    cudaGetSymbolAddress((void**)&k,  g_k);
    cudaGetSymbolAddress((void**)&v,  g_v);
    cudaGetSymbolAddress((void**)&sc, g_sc);
    cudaGetSymbolAddress((void**)&at, g_at);
    cudaGetSymbolAddress((void**)&wo, g_wo);
    cudaGetSymbolAddress((void**)&h,  g_h);
    cudaGetSymbolAddress((void**)&f1, g_f1);
    cudaGetSymbolAddress((void**)&f2, g_f2);
    cudaGetSymbolAddress((void**)&pt, g_pt);

    k_embed<<<BS, 256>>>(ids, emb, x);

    k_sgemm<0><<<dim3(Ee / 128, BS / 128), 256>>>(x, Wq, bq, q, BS, Ee, Ee);
    k_sgemm<0><<<dim3(Ee / 128, BS / 128), 256>>>(x, Wk, bk, k, BS, Ee, Ee);
    k_sgemm<0><<<dim3(Ee / 128, BS / 128), 256>>>(x, Wv, bv, v, BS, Ee, Ee);

    k_scores<<<dim3(Ss / 64, Ss / 64, BH), 256>>>(q, k, sc);
    k_softmax<<<BH * Ss, 256>>>(sc, mask);
    k_ctx<<<dim3(Ss / 64, BH), 256>>>(sc, v, at);

    k_sgemm<0><<<dim3(Ee / 128, BS / 128), 256>>>(at, Wo, bo, wo, BS, Ee, Ee);
    k_ln<<<BS, 256>>>(wo, x, lg, lb, h);

    k_sgemm<1><<<dim3(Ff / 128, BS / 128), 256>>>(h, W1, b1, f1, BS, Ff, Ee);
    k_sgemm<0><<<dim3(Ee / 128, BS / 128), 256>>>(f1, W2, b2, f2, BS, Ee, Ff);

    k_pmean<<<dim3(Ee / 256, Bb, 64), 256>>>(f2, pt);
    k_final<<<1, 384>>>(pt, Wp, bp, (float*)d_out);
}

// round 3
// speedup vs baseline: 1.9656x; 1.9656x over previous
#include <cuda_runtime.h>
#include <cuda_bf16.h>
#include <math.h>

// Problem dims
#define Bb 4
#define Ss 2048
#define Ee 1024
#define Hh 16
#define Dd 64
#define Ff 4096
constexpr int BS = Bb * Ss;   // 8192 tokens
constexpr int BH = Bb * Hh;   // 64 (batch*heads)

// ---------------- scratch (device globals; no allocation allowed) -----------
__device__ float g_x [BS * Ee];
__device__ float g_q [BS * Ee];
__device__ float g_k [BS * Ee];
__device__ float g_v [BS * Ee];
__device__ float g_sc[(size_t)BH * Ss * Ss];   // scores/probs 1 GiB
__device__ float g_at[BS * Ee];
__device__ float g_wo[BS * Ee];
__device__ float g_h [BS * Ee];
__device__ float g_f1[(size_t)BS * Ff];
__device__ float g_f2[BS * Ee];
__device__ float g_pt[64 * Bb * Ee];

// ---------------- mma helpers ----------------
__device__ __forceinline__ unsigned sptr(const void* p) {
    unsigned a;
    asm("{ .reg .u64 t; cvta.to.shared.u64 t, %1; cvt.u32.u64 %0, t; }"
        : "=r"(a) : "l"(p));
    return a;
}
__device__ __forceinline__ void ldsm4(unsigned* r, unsigned a) {
    asm volatile("ldmatrix.sync.aligned.m8n8.x4.shared.b16 {%0,%1,%2,%3}, [%4];"
                 : "=r"(r[0]), "=r"(r[1]), "=r"(r[2]), "=r"(r[3]) : "r"(a));
}
__device__ __forceinline__ void ldsm2(unsigned* r, unsigned a) {
    asm volatile("ldmatrix.sync.aligned.m8n8.x2.shared.b16 {%0,%1}, [%2];"
                 : "=r"(r[0]), "=r"(r[1]) : "r"(a));
}
__device__ __forceinline__ void ldsm2t(unsigned* r, unsigned a) {
    asm volatile("ldmatrix.sync.aligned.m8n8.x2.trans.shared.b16 {%0,%1}, [%2];"
                 : "=r"(r[0]), "=r"(r[1]) : "r"(a));
}
__device__ __forceinline__ void mma16816(float* c, const unsigned* a, const unsigned* b) {
    asm volatile(
        "mma.sync.aligned.m16n8k16.row.col.f32.bf16.bf16.f32 "
        "{%0,%1,%2,%3}, {%4,%5,%6,%7}, {%8,%9}, {%0,%1,%2,%3};"
        : "+f"(c[0]), "+f"(c[1]), "+f"(c[2]), "+f"(c[3])
        : "r"(a[0]), "r"(a[1]), "r"(a[2]), "r"(a[3]), "r"(b[0]), "r"(b[1]));
}
__device__ __forceinline__ void split_store(float v, __nv_bfloat16* hi, __nv_bfloat16* lo) {
    __nv_bfloat16 h = __float2bfloat16(v);
    *hi = h;
    *lo = __float2bfloat16(v - __bfloat162float(h));
}
__device__ __forceinline__ float gelu_exact(float t) {
    return 0.5f * t * (1.0f + erff(t * 0.70710678118654752f));
}

// ---------------- embedding gather ----------------
__global__ void k_embed(const int* __restrict__ ids,
                        const float* __restrict__ emb,
                        float* __restrict__ x) {
    int t = blockIdx.x;
    int id = ids[t];
    const float4* src = (const float4*)(emb + (size_t)id * Ee);
    float4* dst = (float4*)(x + (size_t)t * Ee);
    dst[threadIdx.x] = src[threadIdx.x];
}

// ---------------- tensor-core GEMM: C[M,N] = A@B + bias (opt gelu) ----------
// BM=128 BN=128 BK=32. 256 threads = 8 warps (2m x 4n), warp tile 64x32.
// fp32 inputs split on the fly into bf16 hi/lo; 3 HMMA per logical MMA.
template <int EPI>
__global__ __launch_bounds__(256) void k_mgemm(
    const float* __restrict__ A, const float* __restrict__ Bm,
    const float* __restrict__ bias, float* __restrict__ C,
    int M, int N, int K) {
    __shared__ __nv_bfloat16 Ah[128][40], Al[128][40];
    __shared__ __nv_bfloat16 Bh[32][136], Bl[32][136];
    int tid = threadIdx.x;
    int warp = tid >> 5, lane = tid & 31;
    int wm = warp >> 2, wn = warp & 3;
    const float* Ap = A + (size_t)blockIdx.y * 128 * K;
    const float* Bp = Bm + (size_t)blockIdx.x * 128;

    float acc[4][4][4];
#pragma unroll
    for (int i = 0; i < 4; i++)
#pragma unroll
        for (int j = 0; j < 4; j++)
#pragma unroll
            for (int f = 0; f < 4; f++) acc[i][j][f] = 0.f;

    for (int k0 = 0; k0 < K; k0 += 32) {
#pragma unroll
        for (int l = 0; l < 4; l++) {            // A tile 128x32
            int idx = tid + l * 256;
            int r = idx >> 3, c = (idx & 7) * 4;
            float4 v = *(const float4*)(Ap + (size_t)r * K + k0 + c);
            split_store(v.x, &Ah[r][c + 0], &Al[r][c + 0]);
            split_store(v.y, &Ah[r][c + 1], &Al[r][c + 1]);
            split_store(v.z, &Ah[r][c + 2], &Al[r][c + 2]);
            split_store(v.w, &Ah[r][c + 3], &Al[r][c + 3]);
        }
#pragma unroll
        for (int l = 0; l < 4; l++) {            // B tile 32x128
            int idx = tid + l * 256;
            int r = idx >> 5, c = (idx & 31) * 4;
            float4 v = *(const float4*)(Bp + (size_t)(k0 + r) * N + c);
            split_store(v.x, &Bh[r][c + 0], &Bl[r][c + 0]);
            split_store(v.y, &Bh[r][c + 1], &Bl[r][c + 1]);
            split_store(v.z, &Bh[r][c + 2], &Bl[r][c + 2]);
            split_store(v.w, &Bh[r][c + 3], &Bl[r][c + 3]);
        }
        __syncthreads();
#pragma unroll
        for (int ks = 0; ks < 32; ks += 16) {
            unsigned ah[4][4], al[4][4], bh[4][2], bl[4][2];
#pragma unroll
            for (int mi = 0; mi < 4; mi++) {
                int row = wm * 64 + mi * 16 + (lane & 15);
                int ce = ks + (lane >> 4) * 8;
                ldsm4(ah[mi], sptr(&Ah[row][ce]));
                ldsm4(al[mi], sptr(&Al[row][ce]));
            }
#pragma unroll
            for (int ni = 0; ni < 4; ni++) {
                int kr = ks + (lane & 15);
                int col = wn * 32 + ni * 8;
                ldsm2t(bh[ni], sptr(&Bh[kr][col]));
                ldsm2t(bl[ni], sptr(&Bl[kr][col]));
            }
#pragma unroll
            for (int mi = 0; mi < 4; mi++)
#pragma unroll
                for (int ni = 0; ni < 4; ni++) {
                    mma16816(acc[mi][ni], ah[mi], bh[ni]);
                    mma16816(acc[mi][ni], ah[mi], bl[ni]);
                    mma16816(acc[mi][ni], al[mi], bh[ni]);
                }
        }
        __syncthreads();
    }

    int r0 = blockIdx.y * 128 + wm * 64;
    int c0 = blockIdx.x * 128 + wn * 32;
    int lr = lane >> 2, lc = (lane & 3) * 2;
#pragma unroll
    for (int mi = 0; mi < 4; mi++) {
#pragma unroll
        for (int ni = 0; ni < 4; ni++) {
            int col = c0 + ni * 8 + lc;
            float b0 = bias[col], b1 = bias[col + 1];
            int rA = r0 + mi * 16 + lr, rB = rA + 8;
            float v0 = acc[mi][ni][0] + b0, v1 = acc[mi][ni][1] + b1;
            float v2 = acc[mi][ni][2] + b0, v3 = acc[mi][ni][3] + b1;
            if (EPI == 1) {
                v0 = gelu_exact(v0); v1 = gelu_exact(v1);
                v2 = gelu_exact(v2); v3 = gelu_exact(v3);
            }
            C[(size_t)rA * N + col] = v0; C[(size_t)rA * N + col + 1] = v1;
            C[(size_t)rB * N + col] = v2; C[(size_t)rB * N + col + 1] = v3;
        }
    }
}

// ---------------- scores: S = Q·K^T / 8 (tensor cores) ----------------
// BM=128 q rows, BN=128 keys, K=64 (two BK=32 iters). Warp tile 64x32.
__global__ __launch_bounds__(256) void k_scores_mma(
    const float* __restrict__ q, const float* __restrict__ k,
    float* __restrict__ sc) {
    __shared__ __nv_bfloat16 Qh[128][40], Ql[128][40];
    __shared__ __nv_bfloat16 Kh[128][40], Kl[128][40];
    int bh = blockIdx.z;
    int b = bh / Hh, h = bh % Hh;
    int q0 = blockIdx.y * 128, n0 = blockIdx.x * 128;
    int tid = threadIdx.x;
    int warp = tid >> 5, lane = tid & 31;
    int wm = warp >> 2, wn = warp & 3;
    const float* qb = q + ((size_t)(b * Ss + q0)) * Ee + h * Dd;
    const float* kb = k + ((size_t)(b * Ss + n0)) * Ee + h * Dd;

    float acc[4][4][4];
#pragma unroll
    for (int i = 0; i < 4; i++)
#pragma unroll
        for (int j = 0; j < 4; j++)
#pragma unroll
            for (int f = 0; f < 4; f++) acc[i][j][f] = 0.f;

    for (int k0 = 0; k0 < Dd; k0 += 32) {
#pragma unroll
        for (int l = 0; l < 4; l++) {
            int idx = tid + l * 256;
            int r = idx >> 3, c = (idx & 7) * 4;
            float4 vq = *(const float4*)(qb + (size_t)r * Ee + k0 + c);
            split_store(vq.x, &Qh[r][c + 0], &Ql[r][c + 0]);
            split_store(vq.y, &Qh[r][c + 1], &Ql[r][c + 1]);
            split_store(vq.z, &Qh[r][c + 2], &Ql[r][c + 2]);
            split_store(vq.w, &Qh[r][c + 3], &Ql[r][c + 3]);
            float4 vk = *(const float4*)(kb + (size_t)r * Ee + k0 + c);
            split_store(vk.x, &Kh[r][c + 0], &Kl[r][c + 0]);
            split_store(vk.y, &Kh[r][c + 1], &Kl[r][c + 1]);
            split_store(vk.z, &Kh[r][c + 2], &Kl[r][c + 2]);
            split_store(vk.w, &Kh[r][c + 3], &Kl[r][c + 3]);
        }
        __syncthreads();
#pragma unroll
        for (int ks = 0; ks < 32; ks += 16) {
            unsigned ah[4][4], al[4][4], bh2[4][2], bl2[4][2];
#pragma unroll
            for (int mi = 0; mi < 4; mi++) {
                int row = wm * 64 + mi * 16 + (lane & 15);
                int ce = ks + (lane >> 4) * 8;
                ldsm4(ah[mi], sptr(&Qh[row][ce]));
                ldsm4(al[mi], sptr(&Ql[row][ce]));
            }
#pragma unroll
            for (int ni = 0; ni < 4; ni++) {
                // B = K^T: K row-major [key][d] is exactly col-major [d][key]
                int row = wn * 32 + ni * 8 + (lane & 7);
                int ce = ks + ((lane >> 3) & 1) * 8;
                ldsm2(bh2[ni], sptr(&Kh[row][ce]));
                ldsm2(bl2[ni], sptr(&Kl[row][ce]));
            }
#pragma unroll
            for (int mi = 0; mi < 4; mi++)
#pragma unroll
                for (int ni = 0; ni < 4; ni++) {
                    mma16816(acc[mi][ni], ah[mi], bh2[ni]);
                    mma16816(acc[mi][ni], ah[mi], bl2[ni]);
                    mma16816(acc[mi][ni], al[mi], bh2[ni]);
                }
        }
        __syncthreads();
    }

    const float scale = 0.125f;
    int lr = lane >> 2, lc = (lane & 3) * 2;
#pragma unroll
    for (int mi = 0; mi < 4; mi++) {
#pragma unroll
        for (int ni = 0; ni < 4; ni++) {
            int row = q0 + wm * 64 + mi * 16 + lr;
            int col = n0 + wn * 32 + ni * 8 + lc;
            size_t oA = ((size_t)bh * Ss + row) * Ss + col;
            size_t oB = ((size_t)bh * Ss + row + 8) * Ss + col;
            sc[oA]     = acc[mi][ni][0] * scale;
            sc[oA + 1] = acc[mi][ni][1] * scale;
            sc[oB]     = acc[mi][ni][2] * scale;
            sc[oB + 1] = acc[mi][ni][3] * scale;
        }
    }
}

// ---------------- row softmax (with mask) ----------------
__global__ void k_softmax(float* __restrict__ sc, const int* __restrict__ mask) {
    __shared__ float red[256];
    size_t base = (size_t)blockIdx.x * Ss;
    int b = blockIdx.x / (Hh * Ss);
    const int* mrow = mask + b * Ss;
    int tid = threadIdx.x;
    float vals[8];
    float mx = -INFINITY;
#pragma unroll
    for (int i = 0; i < 8; i++) {
        int c = i * 256 + tid;
        float v = sc[base + c];
        if (mrow[c] == 0) v = -INFINITY;
        vals[i] = v;
        mx = fmaxf(mx, v);
    }
    red[tid] = mx; __syncthreads();
    for (int s = 128; s > 0; s >>= 1) {
        if (tid < s) red[tid] = fmaxf(red[tid], red[tid + s]);
        __syncthreads();
    }
    mx = red[0]; __syncthreads();
    float sum = 0.f;
#pragma unroll
    for (int i = 0; i < 8; i++) {
        float e = __expf(vals[i] - mx);
        vals[i] = e;
        sum += e;
    }
    red[tid] = sum; __syncthreads();
    for (int s = 128; s > 0; s >>= 1) {
        if (tid < s) red[tid] += red[tid + s];
        __syncthreads();
    }
    float inv = 1.0f / red[0];
#pragma unroll
    for (int i = 0; i < 8; i++) {
        int c = i * 256 + tid;
        sc[base + c] = vals[i] * inv;
    }
}

// ---------------- ctx = P @ V (tensor cores) ----------------
// BM=128 q rows, BN=64 (=D), BK=32, K=2048. 8 warps (4m x 2n), warp 32x32.
__global__ __launch_bounds__(256) void k_ctx_mma(
    const float* __restrict__ sc, const float* __restrict__ v,
    float* __restrict__ o) {
    __shared__ __nv_bfloat16 Ph[128][40], Pl[128][40];
    __shared__ __nv_bfloat16 Vh[32][72], Vl[32][72];
    int bh = blockIdx.y;
    int b = bh / Hh, h = bh % Hh;
    int q0 = blockIdx.x * 128;
    int tid = threadIdx.x;
    int warp = tid >> 5, lane = tid & 31;
    int wm = warp >> 1, wn = warp & 1;

    float acc[2][4][4];
#pragma unroll
    for (int i = 0; i < 2; i++)
#pragma unroll
        for (int j = 0; j < 4; j++)
#pragma unroll
            for (int f = 0; f < 4; f++) acc[i][j][f] = 0.f;

    for (int kt = 0; kt < Ss; kt += 32) {
#pragma unroll
        for (int l = 0; l < 4; l++) {            // P tile 128x32
            int idx = tid + l * 256;
            int r = idx >> 3, c = (idx & 7) * 4;
            float4 vp = *(const float4*)(sc + ((size_t)bh * Ss + q0 + r) * Ss + kt + c);
            split_store(vp.x, &Ph[r][c + 0], &Pl[r][c + 0]);
            split_store(vp.y, &Ph[r][c + 1], &Pl[r][c + 1]);
            split_store(vp.z, &Ph[r][c + 2], &Pl[r][c + 2]);
            split_store(vp.w, &Ph[r][c + 3], &Pl[r][c + 3]);
        }
#pragma unroll
        for (int l = 0; l < 2; l++) {            // V tile 32x64
            int idx = tid + l * 256;
            int r = idx >> 4, c = (idx & 15) * 4;
            float4 vv = *(const float4*)(v + ((size_t)(b * Ss + kt + r)) * Ee + h * Dd + c);
            split_store(vv.x, &Vh[r][c + 0], &Vl[r][c + 0]);
            split_store(vv.y, &Vh[r][c + 1], &Vl[r][c + 1]);
            split_store(vv.z, &Vh[r][c + 2], &Vl[r][c + 2]);
            split_store(vv.w, &Vh[r][c + 3], &Vl[r][c + 3]);
        }
        __syncthreads();
#pragma unroll
        for (int ks = 0; ks < 32; ks += 16) {
            unsigned ah[2][4], al[2][4], bh2[4][2], bl2[4][2];
#pragma unroll
            for (int mi = 0; mi < 2; mi++) {
                int row = wm * 32 + mi * 16 + (lane & 15);
                int ce = ks + (lane >> 4) * 8;
                ldsm4(ah[mi], sptr(&Ph[row][ce]));
                ldsm4(al[mi], sptr(&Pl[row][ce]));
            }
#pragma unroll
            for (int ni = 0; ni < 4; ni++) {
                int kr = ks + (lane & 15);
                int col = wn * 32 + ni * 8;
                ldsm2t(bh2[ni], sptr(&Vh[kr][col]));
                ldsm2t(bl2[ni], sptr(&Vl[kr][col]));
            }
#pragma unroll
            for (int mi = 0; mi < 2; mi++)
#pragma unroll
                for (int ni = 0; ni < 4; ni++) {
                    mma16816(acc[mi][ni], ah[mi], bh2[ni]);
                    mma16816(acc[mi][ni], ah[mi], bl2[ni]);
                    mma16816(acc[mi][ni], al[mi], bh2[ni]);
                }
        }
        __syncthreads();
    }

    int lr = lane >> 2, lc = (lane & 3) * 2;
#pragma unroll
    for (int mi = 0; mi < 2; mi++) {
#pragma unroll
        for (int ni = 0; ni < 4; ni++) {
            int row = q0 + wm * 32 + mi * 16 + lr;
            int col = wn * 32 + ni * 8 + lc;
            size_t oA = ((size_t)(b * Ss + row)) * Ee + h * Dd + col;
            size_t oB = ((size_t)(b * Ss + row + 8)) * Ee + h * Dd + col;
            o[oA]     = acc[mi][ni][0];
            o[oA + 1] = acc[mi][ni][1];
            o[oB]     = acc[mi][ni][2];
            o[oB + 1] = acc[mi][ni][3];
        }
    }
}

// ---------------- residual + layernorm ----------------
__global__ void k_ln(const float* __restrict__ wo_out,
                     const float* __restrict__ x,
                     const float* __restrict__ g,
                     const float* __restrict__ be,
                     float* __restrict__ out) {
    __shared__ float red[256];
    __shared__ float s_mu, s_rstd;
    int t = blockIdx.x;
    int tid = threadIdx.x;
    const float* pa = wo_out + (size_t)t * Ee;
    const float* px = x + (size_t)t * Ee;
    float loc[4];
    float sum = 0.f;
#pragma unroll
    for (int i = 0; i < 4; i++) {
        int idx = i * 256 + tid;
        float vv = pa[idx] + px[idx];
        loc[i] = vv;
        sum += vv;
    }
    red[tid] = sum; __syncthreads();
    for (int s = 128; s > 0; s >>= 1) {
        if (tid < s) red[tid] += red[tid + s];
        __syncthreads();
    }
    if (tid == 0) s_mu = red[0] * (1.0f / Ee);
    __syncthreads();
    float mu = s_mu;
    float vs = 0.f;
#pragma unroll
    for (int i = 0; i < 4; i++) {
        float d = loc[i] - mu;
        vs += d * d;
    }
    red[tid] = vs; __syncthreads();
    for (int s = 128; s > 0; s >>= 1) {
        if (tid < s) red[tid] += red[tid + s];
        __syncthreads();
    }
    if (tid == 0) s_rstd = rsqrtf(red[0] * (1.0f / Ee) + 1e-5f);
    __syncthreads();
    float rstd = s_rstd;
#pragma unroll
    for (int i = 0; i < 4; i++) {
        int idx = i * 256 + tid;
        out[(size_t)t * Ee + idx] = (loc[i] - mu) * rstd * g[idx] + be[idx];
    }
}

// ---------------- partial column sums of ff2 ----------------
__global__ void k_pmean(const float* __restrict__ f2, float* __restrict__ part) {
    int e = blockIdx.x * 256 + threadIdx.x;
    int b = blockIdx.y;
    int p = blockIdx.z;
    float s = 0.f;
    int s0 = p * 32;
    for (int i = 0; i < 32; i++)
        s += f2[((size_t)(b * Ss + s0 + i)) * Ee + e];
    part[((size_t)p * Bb + b) * Ee + e] = s;
}

// ---------------- final: out[b][j] = (mean_s ff) @ Wp + bp ----------------
__global__ void k_final(const float* __restrict__ part,
                        const float* __restrict__ Wp,
                        const float* __restrict__ bp,
                        float* __restrict__ out) {
    int w = threadIdx.x >> 5;
    int lane = threadIdx.x & 31;
    if (w >= 12) return;
    int b = w / 3, j = w % 3;
    float acc = 0.f;
    for (int e = lane; e < Ee; e += 32) {
        float s = 0.f;
#pragma unroll
        for (int p = 0; p < 64; p++)
            s += part[((size_t)p * Bb + b) * Ee + e];
        acc += s * Wp[e * 3 + j];
    }
#pragma unroll
    for (int o = 16; o > 0; o >>= 1)
        acc += __shfl_down_sync(0xffffffff, acc, o);
    if (lane == 0) out[b * 3 + j] = acc * (1.0f / Ss) + bp[j];
}

// ---------------- launch ----------------
extern "C" void kernel_launch(void* const* d_in, const int* in_sizes, int n_in,
                              void* d_out, int out_size) {
    const int*   ids  = (const int*)d_in[0];
    const int*   mask = (const int*)d_in[1];
    const float* emb  = (const float*)d_in[2];
    const float* Wq = (const float*)d_in[3],  *bq = (const float*)d_in[4];
    const float* Wk = (const float*)d_in[5],  *bk = (const float*)d_in[6];
    const float* Wv = (const float*)d_in[7],  *bv = (const float*)d_in[8];
    const float* Wo = (const float*)d_in[9],  *bo = (const float*)d_in[10];
    const float* lg = (const float*)d_in[11], *lb = (const float*)d_in[12];
    const float* W1 = (const float*)d_in[13], *b1 = (const float*)d_in[14];
    const float* W2 = (const float*)d_in[15], *b2 = (const float*)d_in[16];
    const float* Wp = (const float*)d_in[17], *bp = (const float*)d_in[18];

    float *x, *q, *k, *v, *sc, *at, *wo, *h, *f1, *f2, *pt;
    cudaGetSymbolAddress((void**)&x,  g_x);
    cudaGetSymbolAddress((void**)&q,  g_q);
    cudaGetSymbolAddress((void**)&k,  g_k);
    cudaGetSymbolAddress((void**)&v,  g_v);
    cudaGetSymbolAddress((void**)&sc, g_sc);
    cudaGetSymbolAddress((void**)&at, g_at);
    cudaGetSymbolAddress((void**)&wo, g_wo);
    cudaGetSymbolAddress((void**)&h,  g_h);
    cudaGetSymbolAddress((void**)&f1, g_f1);
    cudaGetSymbolAddress((void**)&f2, g_f2);
    cudaGetSymbolAddress((void**)&pt, g_pt);

    k_embed<<<BS, 256>>>(ids, emb, x);

    k_mgemm<0><<<dim3(Ee / 128, BS / 128), 256>>>(x, Wq, bq, q, BS, Ee, Ee);
    k_mgemm<0><<<dim3(Ee / 128, BS / 128), 256>>>(x, Wk, bk, k, BS, Ee, Ee);
    k_mgemm<0><<<dim3(Ee / 128, BS / 128), 256>>>(x, Wv, bv, v, BS, Ee, Ee);

    k_scores_mma<<<dim3(Ss / 128, Ss / 128, BH), 256>>>(q, k, sc);
    k_softmax<<<BH * Ss, 256>>>(sc, mask);
    k_ctx_mma<<<dim3(Ss / 128, BH), 256>>>(sc, v, at);

    k_mgemm<0><<<dim3(Ee / 128, BS / 128), 256>>>(at, Wo, bo, wo, BS, Ee, Ee);
    k_ln<<<BS, 256>>>(wo, x, lg, lb, h);

    k_mgemm<1><<<dim3(Ff / 128, BS / 128), 256>>>(h, W1, b1, f1, BS, Ff, Ee);
    k_mgemm<0><<<dim3(Ee / 128, BS / 128), 256>>>(f1, W2, b2, f2, BS, Ee, Ff);

    k_pmean<<<dim3(Ee / 256, Bb, 64), 256>>>(f2, pt);
    k_final<<<1, 384>>>(pt, Wp, bp, (float*)d_out);
}

// round 4
// speedup vs baseline: 2.2280x; 1.1335x over previous
#include <cuda_runtime.h>
#include <cuda_bf16.h>
#include <math.h>

// Problem dims
#define Bb 4
#define Ss 2048
#define Ee 1024
#define Hh 16
#define Dd 64
#define Ff 4096
constexpr int BS = Bb * Ss;   // 8192 tokens
constexpr int BH = Bb * Hh;   // 64 (batch*heads)

// ---------------- scratch (device globals; no allocation allowed) -----------
__device__ float g_x [BS * Ee];
__device__ float g_q [BS * Ee];
__device__ float g_k [BS * Ee];
__device__ float g_v [BS * Ee];
__device__ float g_at[BS * Ee];
__device__ float g_wo[BS * Ee];
__device__ float g_h [BS * Ee];
__device__ float g_f1[(size_t)BS * Ff];
__device__ float g_f2[BS * Ee];
__device__ float g_pt[64 * Bb * Ee];

// ---------------- mma helpers ----------------
__device__ __forceinline__ unsigned sptr(const void* p) {
    unsigned a;
    asm("{ .reg .u64 t; cvta.to.shared.u64 t, %1; cvt.u32.u64 %0, t; }"
        : "=r"(a) : "l"(p));
    return a;
}
__device__ __forceinline__ void ldsm4(unsigned* r, unsigned a) {
    asm volatile("ldmatrix.sync.aligned.m8n8.x4.shared.b16 {%0,%1,%2,%3}, [%4];"
                 : "=r"(r[0]), "=r"(r[1]), "=r"(r[2]), "=r"(r[3]) : "r"(a));
}
__device__ __forceinline__ void ldsm2(unsigned* r, unsigned a) {
    asm volatile("ldmatrix.sync.aligned.m8n8.x2.shared.b16 {%0,%1}, [%2];"
                 : "=r"(r[0]), "=r"(r[1]) : "r"(a));
}
__device__ __forceinline__ void ldsm2t(unsigned* r, unsigned a) {
    asm volatile("ldmatrix.sync.aligned.m8n8.x2.trans.shared.b16 {%0,%1}, [%2];"
                 : "=r"(r[0]), "=r"(r[1]) : "r"(a));
}
__device__ __forceinline__ void mma16816(float* c, const unsigned* a, const unsigned* b) {
    asm volatile(
        "mma.sync.aligned.m16n8k16.row.col.f32.bf16.bf16.f32 "
        "{%0,%1,%2,%3}, {%4,%5,%6,%7}, {%8,%9}, {%0,%1,%2,%3};"
        : "+f"(c[0]), "+f"(c[1]), "+f"(c[2]), "+f"(c[3])
        : "r"(a[0]), "r"(a[1]), "r"(a[2]), "r"(a[3]), "r"(b[0]), "r"(b[1]));
}
__device__ __forceinline__ void split_store(float v, __nv_bfloat16* hi, __nv_bfloat16* lo) {
    __nv_bfloat16 h = __float2bfloat16(v);
    *hi = h;
    *lo = __float2bfloat16(v - __bfloat162float(h));
}
__device__ __forceinline__ unsigned pack2(__nv_bfloat16 a, __nv_bfloat16 b) {
    unsigned short ua = *(unsigned short*)&a, ub = *(unsigned short*)&b;
    return (unsigned)ua | ((unsigned)ub << 16);
}
__device__ __forceinline__ float gelu_exact(float t) {
    return 0.5f * t * (1.0f + erff(t * 0.70710678118654752f));
}

// ---------------- embedding gather ----------------
__global__ void k_embed(const int* __restrict__ ids,
                        const float* __restrict__ emb,
                        float* __restrict__ x) {
    int t = blockIdx.x;
    int id = ids[t];
    const float4* src = (const float4*)(emb + (size_t)id * Ee);
    float4* dst = (float4*)(x + (size_t)t * Ee);
    dst[threadIdx.x] = src[threadIdx.x];
}

// ---------------- tensor-core GEMM with register prefetch pipeline ----------
// BM=128 BN=128 BK=32. 256 threads = 8 warps (2m x 4n), warp tile 64x32.
template <int EPI>
__global__ __launch_bounds__(256, 1) void k_mgemm(
    const float* __restrict__ A, const float* __restrict__ Bm,
    const float* __restrict__ bias, float* __restrict__ C,
    int M, int N, int K) {
    __shared__ __nv_bfloat16 Ah[128][40], Al[128][40];
    __shared__ __nv_bfloat16 Bh[32][136], Bl[32][136];
    int tid = threadIdx.x;
    int warp = tid >> 5, lane = tid & 31;
    int wm = warp >> 2, wn = warp & 3;
    const float* Ap = A + (size_t)blockIdx.y * 128 * K;
    const float* Bp = Bm + (size_t)blockIdx.x * 128;

    float acc[4][4][4];
#pragma unroll
    for (int i = 0; i < 4; i++)
#pragma unroll
        for (int j = 0; j < 4; j++)
#pragma unroll
            for (int f = 0; f < 4; f++) acc[i][j][f] = 0.f;

    // A-tile thread mapping: r = idx>>3, c = (idx&7)*4  (128x32)
    // B-tile thread mapping: r = idx>>5, c = (idx&31)*4 (32x128)
    float4 ra[4], rb[4];
#pragma unroll
    for (int l = 0; l < 4; l++) {
        int idx = tid + l * 256;
        ra[l] = *(const float4*)(Ap + (size_t)(idx >> 3) * K + ((idx & 7) * 4));
        rb[l] = *(const float4*)(Bp + (size_t)(idx >> 5) * N + ((idx & 31) * 4));
    }

    for (int k0 = 0; k0 < K; k0 += 32) {
        // commit prefetched tile to smem (split hi/lo)
#pragma unroll
        for (int l = 0; l < 4; l++) {
            int idx = tid + l * 256;
            int r = idx >> 3, c = (idx & 7) * 4;
            split_store(ra[l].x, &Ah[r][c + 0], &Al[r][c + 0]);
            split_store(ra[l].y, &Ah[r][c + 1], &Al[r][c + 1]);
            split_store(ra[l].z, &Ah[r][c + 2], &Al[r][c + 2]);
            split_store(ra[l].w, &Ah[r][c + 3], &Al[r][c + 3]);
            int r2 = idx >> 5, c2 = (idx & 31) * 4;
            split_store(rb[l].x, &Bh[r2][c2 + 0], &Bl[r2][c2 + 0]);
            split_store(rb[l].y, &Bh[r2][c2 + 1], &Bl[r2][c2 + 1]);
            split_store(rb[l].z, &Bh[r2][c2 + 2], &Bl[r2][c2 + 2]);
            split_store(rb[l].w, &Bh[r2][c2 + 3], &Bl[r2][c2 + 3]);
        }
        __syncthreads();
        // issue next tile's global loads early (overlap with MMAs)
        if (k0 + 32 < K) {
#pragma unroll
            for (int l = 0; l < 4; l++) {
                int idx = tid + l * 256;
                ra[l] = *(const float4*)(Ap + (size_t)(idx >> 3) * K + (k0 + 32) + ((idx & 7) * 4));
                rb[l] = *(const float4*)(Bp + (size_t)((k0 + 32) + (idx >> 5)) * N + ((idx & 31) * 4));
            }
        }
#pragma unroll
        for (int ks = 0; ks < 32; ks += 16) {
            unsigned ah[4][4], al[4][4];
#pragma unroll
            for (int mi = 0; mi < 4; mi++) {
                int row = wm * 64 + mi * 16 + (lane & 15);
                int ce = ks + (lane >> 4) * 8;
                ldsm4(ah[mi], sptr(&Ah[row][ce]));
                ldsm4(al[mi], sptr(&Al[row][ce]));
            }
#pragma unroll
            for (int ni = 0; ni < 4; ni++) {
                unsigned bh[2], bl[2];
                int kr = ks + (lane & 15);
                int col = wn * 32 + ni * 8;
                ldsm2t(bh, sptr(&Bh[kr][col]));
                ldsm2t(bl, sptr(&Bl[kr][col]));
#pragma unroll
                for (int mi = 0; mi < 4; mi++) {
                    mma16816(acc[mi][ni], ah[mi], bh);
                    mma16816(acc[mi][ni], ah[mi], bl);
                    mma16816(acc[mi][ni], al[mi], bh);
                }
            }
        }
        __syncthreads();
    }

    int r0 = blockIdx.y * 128 + wm * 64;
    int c0 = blockIdx.x * 128 + wn * 32;
    int lr = lane >> 2, lc = (lane & 3) * 2;
#pragma unroll
    for (int mi = 0; mi < 4; mi++) {
#pragma unroll
        for (int ni = 0; ni < 4; ni++) {
            int col = c0 + ni * 8 + lc;
            float b0 = bias[col], b1 = bias[col + 1];
            int rA = r0 + mi * 16 + lr, rB = rA + 8;
            float v0 = acc[mi][ni][0] + b0, v1 = acc[mi][ni][1] + b1;
            float v2 = acc[mi][ni][2] + b0, v3 = acc[mi][ni][3] + b1;
            if (EPI == 1) {
                v0 = gelu_exact(v0); v1 = gelu_exact(v1);
                v2 = gelu_exact(v2); v3 = gelu_exact(v3);
            }
            C[(size_t)rA * N + col] = v0; C[(size_t)rA * N + col + 1] = v1;
            C[(size_t)rB * N + col] = v2; C[(size_t)rB * N + col + 1] = v3;
        }
    }
}

// ---------------- fused flash attention ----------------
// One block: 64 q rows of one (b,h). 128 threads = 4 warps, 16 q rows/warp.
// Loop over 32 kv tiles of 64 keys. S stays in registers; online softmax;
// score C-frags reused directly as A-frags for P@V. 3-term split-bf16 both MMAs.
__global__ __launch_bounds__(128) void k_flash(
    const float* __restrict__ q, const float* __restrict__ k,
    const float* __restrict__ v, const int* __restrict__ mask,
    float* __restrict__ o) {
    __shared__ __align__(16) char smraw[36864];
    __nv_bfloat16 (*Qh)[72] = (__nv_bfloat16(*)[72])(smraw);
    __nv_bfloat16 (*Ql)[72] = (__nv_bfloat16(*)[72])(smraw + 9216);
    __nv_bfloat16 (*Kh)[72] = (__nv_bfloat16(*)[72])(smraw);
    __nv_bfloat16 (*Kl)[72] = (__nv_bfloat16(*)[72])(smraw + 9216);
    __nv_bfloat16 (*Vh)[72] = (__nv_bfloat16(*)[72])(smraw + 18432);
    __nv_bfloat16 (*Vl)[72] = (__nv_bfloat16(*)[72])(smraw + 27648);
    __shared__ float madd[Ss];

    int bh = blockIdx.y;
    int b = bh >> 4, h = bh & 15;
    int q0 = blockIdx.x * 64;
    int tid = threadIdx.x, warp = tid >> 5, lane = tid & 31;
    int g = lane >> 2, t = lane & 3;

    const float* qb = q + ((size_t)(b * Ss + q0)) * Ee + h * Dd;
    const float* kb = k + ((size_t)(b * Ss)) * Ee + h * Dd;
    const float* vb = v + ((size_t)(b * Ss)) * Ee + h * Dd;

    // mask additive vector
    for (int i = tid; i < Ss; i += 128)
        madd[i] = mask[b * Ss + i] ? 0.f : -1e30f;

    // load Q tile 64x64 into smem (split)
#pragma unroll
    for (int l0 = 0; l0 < 8; l0++) {
        int idx = tid + l0 * 128;
        int r = idx >> 4, c = (idx & 15) * 4;
        float4 vq = *(const float4*)(qb + (size_t)r * Ee + c);
        split_store(vq.x, &Qh[r][c + 0], &Ql[r][c + 0]);
        split_store(vq.y, &Qh[r][c + 1], &Ql[r][c + 1]);
        split_store(vq.z, &Qh[r][c + 2], &Ql[r][c + 2]);
        split_store(vq.w, &Qh[r][c + 3], &Ql[r][c + 3]);
    }
    __syncthreads();

    // preload Q fragments (constant across kv loop)
    unsigned qfh[4][4], qfl[4][4];
#pragma unroll
    for (int ks = 0; ks < 4; ks++) {
        int row = warp * 16 + (lane & 15);
        int ce = ks * 16 + (lane >> 4) * 8;
        ldsm4(qfh[ks], sptr(&Qh[row][ce]));
        ldsm4(qfl[ks], sptr(&Ql[row][ce]));
    }
    __syncthreads();   // Q smem region is now dead; reuse for K/V

    float oacc[8][4];
#pragma unroll
    for (int i = 0; i < 8; i++)
#pragma unroll
        for (int f = 0; f < 4; f++) oacc[i][f] = 0.f;
    float m0 = -INFINITY, m1 = -INFINITY;
    float l0s = 0.f, l1s = 0.f;

    for (int kt = 0; kt < Ss; kt += 64) {
        // load K,V tiles (64x64 each, split)
#pragma unroll
        for (int l0 = 0; l0 < 8; l0++) {
            int idx = tid + l0 * 128;
            int r = idx >> 4, c = (idx & 15) * 4;
            float4 vk = *(const float4*)(kb + (size_t)(kt + r) * Ee + c);
            split_store(vk.x, &Kh[r][c + 0], &Kl[r][c + 0]);
            split_store(vk.y, &Kh[r][c + 1], &Kl[r][c + 1]);
            split_store(vk.z, &Kh[r][c + 2], &Kl[r][c + 2]);
            split_store(vk.w, &Kh[r][c + 3], &Kl[r][c + 3]);
            float4 vv = *(const float4*)(vb + (size_t)(kt + r) * Ee + c);
            split_store(vv.x, &Vh[r][c + 0], &Vl[r][c + 0]);
            split_store(vv.y, &Vh[r][c + 1], &Vl[r][c + 1]);
            split_store(vv.z, &Vh[r][c + 2], &Vl[r][c + 2]);
            split_store(vv.w, &Vh[r][c + 3], &Vl[r][c + 3]);
        }
        __syncthreads();

        // S = Q K^T  (16 rows x 64 keys per warp)
        float sacc[8][4];
#pragma unroll
        for (int i = 0; i < 8; i++)
#pragma unroll
            for (int f = 0; f < 4; f++) sacc[i][f] = 0.f;
#pragma unroll
        for (int ks = 0; ks < 4; ks++) {
#pragma unroll
            for (int ni = 0; ni < 8; ni++) {
                unsigned bh2[2], bl2[2];
                int row = ni * 8 + (lane & 7);
                int ce = ks * 16 + ((lane >> 3) & 1) * 8;
                ldsm2(bh2, sptr(&Kh[row][ce]));
                ldsm2(bl2, sptr(&Kl[row][ce]));
                mma16816(sacc[ni], qfh[ks], bh2);
                mma16816(sacc[ni], qfh[ks], bl2);
                mma16816(sacc[ni], qfl[ks], bh2);
            }
        }

        // scale + mask + row max
        const float scale = 0.125f;
        float mc0 = -INFINITY, mc1 = -INFINITY;
#pragma unroll
        for (int ni = 0; ni < 8; ni++) {
            int col = kt + ni * 8 + 2 * t;
            float ma = madd[col], mb = madd[col + 1];
            float s0 = sacc[ni][0] * scale + ma;
            float s1 = sacc[ni][1] * scale + mb;
            float s2 = sacc[ni][2] * scale + ma;
            float s3 = sacc[ni][3] * scale + mb;
            sacc[ni][0] = s0; sacc[ni][1] = s1;
            sacc[ni][2] = s2; sacc[ni][3] = s3;
            mc0 = fmaxf(mc0, fmaxf(s0, s1));
            mc1 = fmaxf(mc1, fmaxf(s2, s3));
        }
        mc0 = fmaxf(mc0, __shfl_xor_sync(0xffffffffu, mc0, 1));
        mc0 = fmaxf(mc0, __shfl_xor_sync(0xffffffffu, mc0, 2));
        mc1 = fmaxf(mc1, __shfl_xor_sync(0xffffffffu, mc1, 1));
        mc1 = fmaxf(mc1, __shfl_xor_sync(0xffffffffu, mc1, 2));
        float mn0 = fmaxf(m0, mc0), mn1 = fmaxf(m1, mc1);
        float alpha0 = __expf(m0 - mn0), alpha1 = __expf(m1 - mn1);

        // exponentiate, accumulate row sums
        float sum0 = 0.f, sum1 = 0.f;
#pragma unroll
        for (int ni = 0; ni < 8; ni++) {
            float p0 = __expf(sacc[ni][0] - mn0);
            float p1 = __expf(sacc[ni][1] - mn0);
            float p2 = __expf(sacc[ni][2] - mn1);
            float p3 = __expf(sacc[ni][3] - mn1);
            sacc[ni][0] = p0; sacc[ni][1] = p1;
            sacc[ni][2] = p2; sacc[ni][3] = p3;
            sum0 += p0 + p1; sum1 += p2 + p3;
        }
        sum0 += __shfl_xor_sync(0xffffffffu, sum0, 1);
        sum0 += __shfl_xor_sync(0xffffffffu, sum0, 2);
        sum1 += __shfl_xor_sync(0xffffffffu, sum1, 1);
        sum1 += __shfl_xor_sync(0xffffffffu, sum1, 2);
        l0s = l0s * alpha0 + sum0;
        l1s = l1s * alpha1 + sum1;
        m0 = mn0; m1 = mn1;

        // rescale O
#pragma unroll
        for (int ni = 0; ni < 8; ni++) {
            oacc[ni][0] *= alpha0; oacc[ni][1] *= alpha0;
            oacc[ni][2] *= alpha1; oacc[ni][3] *= alpha1;
        }

        // O += P @ V : P frags direct from registers
#pragma unroll
        for (int j = 0; j < 4; j++) {       // kv k-steps of 16
            unsigned pah[4], pal[4];
            {
                float p0 = sacc[2 * j][0], p1 = sacc[2 * j][1];
                float p2 = sacc[2 * j][2], p3 = sacc[2 * j][3];
                float p4 = sacc[2 * j + 1][0], p5 = sacc[2 * j + 1][1];
                float p6 = sacc[2 * j + 1][2], p7 = sacc[2 * j + 1][3];
                __nv_bfloat16 h0 = __float2bfloat16(p0), h1 = __float2bfloat16(p1);
                __nv_bfloat16 h2 = __float2bfloat16(p2), h3 = __float2bfloat16(p3);
                __nv_bfloat16 h4 = __float2bfloat16(p4), h5 = __float2bfloat16(p5);
                __nv_bfloat16 h6 = __float2bfloat16(p6), h7 = __float2bfloat16(p7);
                pah[0] = pack2(h0, h1); pah[1] = pack2(h2, h3);
                pah[2] = pack2(h4, h5); pah[3] = pack2(h6, h7);
                pal[0] = pack2(__float2bfloat16(p0 - __bfloat162float(h0)),
                               __float2bfloat16(p1 - __bfloat162float(h1)));
                pal[1] = pack2(__float2bfloat16(p2 - __bfloat162float(h2)),
                               __float2bfloat16(p3 - __bfloat162float(h3)));
                pal[2] = pack2(__float2bfloat16(p4 - __bfloat162float(h4)),
                               __float2bfloat16(p5 - __bfloat162float(h5)));
                pal[3] = pack2(__float2bfloat16(p6 - __bfloat162float(h6)),
                               __float2bfloat16(p7 - __bfloat162float(h7)));
            }
#pragma unroll
            for (int ni = 0; ni < 8; ni++) {
                unsigned vh2[2], vl2[2];
                int kr = j * 16 + (lane & 15);
                ldsm2t(vh2, sptr(&Vh[kr][ni * 8]));
                ldsm2t(vl2, sptr(&Vl[kr][ni * 8]));
                mma16816(oacc[ni], pah, vh2);
                mma16816(oacc[ni], pal, vh2);
                mma16816(oacc[ni], pah, vl2);
            }
        }
        __syncthreads();
    }

    // epilogue: normalize and write
    float inv0 = 1.0f / l0s, inv1 = 1.0f / l1s;
    int r0 = q0 + warp * 16 + g, r1 = r0 + 8;
#pragma unroll
    for (int ni = 0; ni < 8; ni++) {
        int col = h * Dd + ni * 8 + 2 * t;
        size_t oA = ((size_t)(b * Ss + r0)) * Ee + col;
        size_t oB = ((size_t)(b * Ss + r1)) * Ee + col;
        o[oA]     = oacc[ni][0] * inv0;
        o[oA + 1] = oacc[ni][1] * inv0;
        o[oB]     = oacc[ni][2] * inv1;
        o[oB + 1] = oacc[ni][3] * inv1;
    }
}

// ---------------- residual + layernorm ----------------
__global__ void k_ln(const float* __restrict__ wo_out,
                     const float* __restrict__ x,
                     const float* __restrict__ g,
                     const float* __restrict__ be,
                     float* __restrict__ out) {
    __shared__ float red[256];
    __shared__ float s_mu, s_rstd;
    int t = blockIdx.x;
    int tid = threadIdx.x;
    const float* pa = wo_out + (size_t)t * Ee;
    const float* px = x + (size_t)t * Ee;
    float loc[4];
    float sum = 0.f;
#pragma unroll
    for (int i = 0; i < 4; i++) {
        int idx = i * 256 + tid;
        float vv = pa[idx] + px[idx];
        loc[i] = vv;
        sum += vv;
    }
    red[tid] = sum; __syncthreads();
    for (int s = 128; s > 0; s >>= 1) {
        if (tid < s) red[tid] += red[tid + s];
        __syncthreads();
    }
    if (tid == 0) s_mu = red[0] * (1.0f / Ee);
    __syncthreads();
    float mu = s_mu;
    float vs = 0.f;
#pragma unroll
    for (int i = 0; i < 4; i++) {
        float d = loc[i] - mu;
        vs += d * d;
    }
    red[tid] = vs; __syncthreads();
    for (int s = 128; s > 0; s >>= 1) {
        if (tid < s) red[tid] += red[tid + s];
        __syncthreads();
    }
    if (tid == 0) s_rstd = rsqrtf(red[0] * (1.0f / Ee) + 1e-5f);
    __syncthreads();
    float rstd = s_rstd;
#pragma unroll
    for (int i = 0; i < 4; i++) {
        int idx = i * 256 + tid;
        out[(size_t)t * Ee + idx] = (loc[i] - mu) * rstd * g[idx] + be[idx];
    }
}

// ---------------- partial column sums of ff2 ----------------
__global__ void k_pmean(const float* __restrict__ f2, float* __restrict__ part) {
    int e = blockIdx.x * 256 + threadIdx.x;
    int b = blockIdx.y;
    int p = blockIdx.z;
    float s = 0.f;
    int s0 = p * 32;
    for (int i = 0; i < 32; i++)
        s += f2[((size_t)(b * Ss + s0 + i)) * Ee + e];
    part[((size_t)p * Bb + b) * Ee + e] = s;
}

// ---------------- final: out[b][j] = (mean_s ff) @ Wp + bp ----------------
__global__ void k_final(const float* __restrict__ part,
                        const float* __restrict__ Wp,
                        const float* __restrict__ bp,
                        float* __restrict__ out) {
    int w = threadIdx.x >> 5;
    int lane = threadIdx.x & 31;
    if (w >= 12) return;
    int b = w / 3, j = w % 3;
    float acc = 0.f;
    for (int e = lane; e < Ee; e += 32) {
        float s = 0.f;
#pragma unroll
        for (int p = 0; p < 64; p++)
            s += part[((size_t)p * Bb + b) * Ee + e];
        acc += s * Wp[e * 3 + j];
    }
#pragma unroll
    for (int o = 16; o > 0; o >>= 1)
        acc += __shfl_down_sync(0xffffffff, acc, o);
    if (lane == 0) out[b * 3 + j] = acc * (1.0f / Ss) + bp[j];
}

// ---------------- launch ----------------
extern "C" void kernel_launch(void* const* d_in, const int* in_sizes, int n_in,
                              void* d_out, int out_size) {
    const int*   ids  = (const int*)d_in[0];
    const int*   mask = (const int*)d_in[1];
    const float* emb  = (const float*)d_in[2];
    const float* Wq = (const float*)d_in[3],  *bq = (const float*)d_in[4];
    const float* Wk = (const float*)d_in[5],  *bk = (const float*)d_in[6];
    const float* Wv = (const float*)d_in[7],  *bv = (const float*)d_in[8];
    const float* Wo = (const float*)d_in[9],  *bo = (const float*)d_in[10];
    const float* lg = (const float*)d_in[11], *lb = (const float*)d_in[12];
    const float* W1 = (const float*)d_in[13], *b1 = (const float*)d_in[14];
    const float* W2 = (const float*)d_in[15], *b2 = (const float*)d_in[16];
    const float* Wp = (const float*)d_in[17], *bp = (const float*)d_in[18];

    float *x, *q, *k, *v, *at, *wo, *h, *f1, *f2, *pt;
    cudaGetSymbolAddress((void**)&x,  g_x);
    cudaGetSymbolAddress((void**)&q,  g_q);
    cudaGetSymbolAddress((void**)&k,  g_k);
    cudaGetSymbolAddress((void**)&v,  g_v);
    cudaGetSymbolAddress((void**)&at, g_at);
    cudaGetSymbolAddress((void**)&wo, g_wo);
    cudaGetSymbolAddress((void**)&h,  g_h);
    cudaGetSymbolAddress((void**)&f1, g_f1);
    cudaGetSymbolAddress((void**)&f2, g_f2);
    cudaGetSymbolAddress((void**)&pt, g_pt);

    k_embed<<<BS, 256>>>(ids, emb, x);

    k_mgemm<0><<<dim3(Ee / 128, BS / 128), 256>>>(x, Wq, bq, q, BS, Ee, Ee);
    k_mgemm<0><<<dim3(Ee / 128, BS / 128), 256>>>(x, Wk, bk, k, BS, Ee, Ee);
    k_mgemm<0><<<dim3(Ee / 128, BS / 128), 256>>>(x, Wv, bv, v, BS, Ee, Ee);

    k_flash<<<dim3(Ss / 64, BH), 128>>>(q, k, v, mask, at);

    k_mgemm<0><<<dim3(Ee / 128, BS / 128), 256>>>(at, Wo, bo, wo, BS, Ee, Ee);
    k_ln<<<BS, 256>>>(wo, x, lg, lb, h);

    k_mgemm<1><<<dim3(Ff / 128, BS / 128), 256>>>(h, W1, b1, f1, BS, Ff, Ee);
    k_mgemm<0><<<dim3(Ee / 128, BS / 128), 256>>>(f1, W2, b2, f2, BS, Ee, Ff);

    k_pmean<<<dim3(Ee / 256, Bb, 64), 256>>>(f2, pt);
    k_final<<<1, 384>>>(pt, Wp, bp, (float*)d_out);
}

// round 5
// speedup vs baseline: 2.6730x; 1.1997x over previous
#include <cuda_runtime.h>
#include <cuda_bf16.h>
#include <math.h>

// Problem dims
#define Bb 4
#define Ss 2048
#define Ee 1024
#define Hh 16
#define Dd 64
#define Ff 4096
constexpr int BS = Bb * Ss;   // 8192 tokens
constexpr int BH = Bb * Hh;   // 64

// ---------------- scratch (device globals) -----------
__device__ float g_x [BS * Ee];
__device__ __nv_bfloat16 g_xh[BS * Ee], g_xl[BS * Ee];
__device__ float g_q [BS * Ee];
__device__ float g_k [BS * Ee];
__device__ float g_v [BS * Ee];
__device__ __nv_bfloat16 g_ath[BS * Ee], g_atl[BS * Ee];
__device__ float g_wo[BS * Ee];
__device__ __nv_bfloat16 g_hh[BS * Ee], g_hl[BS * Ee];
__device__ __nv_bfloat16 g_f1h[(size_t)BS * Ff], g_f1l[(size_t)BS * Ff];
__device__ float g_f2[BS * Ee];
__device__ float g_pt[64 * Bb * Ee];
// pre-split weights
__device__ __nv_bfloat16 g_wqh[Ee * Ee], g_wql[Ee * Ee];
__device__ __nv_bfloat16 g_wkh[Ee * Ee], g_wkl[Ee * Ee];
__device__ __nv_bfloat16 g_wvh[Ee * Ee], g_wvl[Ee * Ee];
__device__ __nv_bfloat16 g_woh[Ee * Ee], g_wol[Ee * Ee];
__device__ __nv_bfloat16 g_w1h[Ee * Ff], g_w1l[Ee * Ff];
__device__ __nv_bfloat16 g_w2h[Ff * Ee], g_w2l[Ff * Ee];

// ---------------- helpers ----------------
__device__ __forceinline__ unsigned sptr(const void* p) {
    unsigned a;
    asm("{ .reg .u64 t; cvta.to.shared.u64 t, %1; cvt.u32.u64 %0, t; }"
        : "=r"(a) : "l"(p));
    return a;
}
__device__ __forceinline__ void ldsm4(unsigned* r, unsigned a) {
    asm volatile("ldmatrix.sync.aligned.m8n8.x4.shared.b16 {%0,%1,%2,%3}, [%4];"
                 : "=r"(r[0]), "=r"(r[1]), "=r"(r[2]), "=r"(r[3]) : "r"(a));
}
__device__ __forceinline__ void ldsm2(unsigned* r, unsigned a) {
    asm volatile("ldmatrix.sync.aligned.m8n8.x2.shared.b16 {%0,%1}, [%2];"
                 : "=r"(r[0]), "=r"(r[1]) : "r"(a));
}
__device__ __forceinline__ void ldsm2t(unsigned* r, unsigned a) {
    asm volatile("ldmatrix.sync.aligned.m8n8.x2.trans.shared.b16 {%0,%1}, [%2];"
                 : "=r"(r[0]), "=r"(r[1]) : "r"(a));
}
__device__ __forceinline__ void mma16816(float* c, const unsigned* a, const unsigned* b) {
    asm volatile(
        "mma.sync.aligned.m16n8k16.row.col.f32.bf16.bf16.f32 "
        "{%0,%1,%2,%3}, {%4,%5,%6,%7}, {%8,%9}, {%0,%1,%2,%3};"
        : "+f"(c[0]), "+f"(c[1]), "+f"(c[2]), "+f"(c[3])
        : "r"(a[0]), "r"(a[1]), "r"(a[2]), "r"(a[3]), "r"(b[0]), "r"(b[1]));
}
__device__ __forceinline__ void cpa16(unsigned dst, const void* src) {
    asm volatile("cp.async.cg.shared.global [%0], [%1], 16;"
                 :: "r"(dst), "l"(src));
}
#define CP_COMMIT asm volatile("cp.async.commit_group;" ::: "memory")
#define CP_WAIT(n) asm volatile("cp.async.wait_group %0;" :: "n"(n) : "memory")

__device__ __forceinline__ void split_store(float v, __nv_bfloat16* hi, __nv_bfloat16* lo) {
    __nv_bfloat16 h = __float2bfloat16(v);
    *hi = h;
    *lo = __float2bfloat16(v - __bfloat162float(h));
}
__device__ __forceinline__ unsigned pack2(__nv_bfloat16 a, __nv_bfloat16 b) {
    unsigned short ua = *(unsigned short*)&a, ub = *(unsigned short*)&b;
    return (unsigned)ua | ((unsigned)ub << 16);
}
__device__ __forceinline__ float gelu_exact(float t) {
    return 0.5f * t * (1.0f + erff(t * 0.70710678118654752f));
}

// ---------------- fp32 -> bf16 hi/lo split ----------------
__global__ void k_split(const float* __restrict__ in,
                        __nv_bfloat16* __restrict__ hi,
                        __nv_bfloat16* __restrict__ lo, int n) {
    int i = (blockIdx.x * 256 + threadIdx.x) * 4;
    if (i >= n) return;
    float4 v = *(const float4*)(in + i);
    __nv_bfloat16 hs[4], ls[4];
    split_store(v.x, &hs[0], &ls[0]);
    split_store(v.y, &hs[1], &ls[1]);
    split_store(v.z, &hs[2], &ls[2]);
    split_store(v.w, &hs[3], &ls[3]);
    *(uint2*)(hi + i) = *(uint2*)hs;
    *(uint2*)(lo + i) = *(uint2*)ls;
}

// ---------------- embedding gather (+ split) ----------------
__global__ void k_embed(const int* __restrict__ ids,
                        const float* __restrict__ emb,
                        float* __restrict__ x,
                        __nv_bfloat16* __restrict__ xh,
                        __nv_bfloat16* __restrict__ xl) {
    int t = blockIdx.x;
    int id = ids[t];
    size_t off = (size_t)t * Ee + threadIdx.x * 4;
    float4 v = *(const float4*)(emb + (size_t)id * Ee + threadIdx.x * 4);
    *(float4*)(x + off) = v;
    __nv_bfloat16 hs[4], ls[4];
    split_store(v.x, &hs[0], &ls[0]);
    split_store(v.y, &hs[1], &ls[1]);
    split_store(v.z, &hs[2], &ls[2]);
    split_store(v.w, &hs[3], &ls[3]);
    *(uint2*)(xh + off) = *(uint2*)hs;
    *(uint2*)(xl + off) = *(uint2*)ls;
}

// ---------------- bf16 hi/lo GEMM, cp.async double buffered ----------------
// BM=128 BN=128 BK=32. 256 threads = 8 warps (2m x 4n), warp tile 64x32.
// stage layout (bf16 elems): Ah[128*40]@0, Al@5120, Bh[32*136]@10240, Bl@14592
constexpr int STG = 18944;         // elems per stage
constexpr int SMEM_BYTES = 2 * STG * 2;

__device__ __forceinline__ void issue_tile(
    __nv_bfloat16* st,
    const __nv_bfloat16* __restrict__ Ahg, const __nv_bfloat16* __restrict__ Alg,
    const __nv_bfloat16* __restrict__ Bhg, const __nv_bfloat16* __restrict__ Blg,
    int k0, int K, int N, int by, int bx, int tid) {
#pragma unroll
    for (int l = 0; l < 2; l++) {
        int cid = tid + l * 256;
        int r = cid >> 2, c8 = (cid & 3) * 8;
        cpa16(sptr(st + r * 40 + c8), Ahg + (size_t)(by + r) * K + k0 + c8);
        cpa16(sptr(st + 5120 + r * 40 + c8), Alg + (size_t)(by + r) * K + k0 + c8);
        int rb = cid >> 4, cb = (cid & 15) * 8;
        cpa16(sptr(st + 10240 + rb * 136 + cb), Bhg + (size_t)(k0 + rb) * N + bx + cb);
        cpa16(sptr(st + 14592 + rb * 136 + cb), Blg + (size_t)(k0 + rb) * N + bx + cb);
    }
}

template <int EPI>  // 0: bias->fp32 C   1: bias+gelu->bf16 hi/lo
__global__ __launch_bounds__(256, 2) void k_bgemm(
    const __nv_bfloat16* __restrict__ Ahg, const __nv_bfloat16* __restrict__ Alg,
    const __nv_bfloat16* __restrict__ Bhg, const __nv_bfloat16* __restrict__ Blg,
    const float* __restrict__ bias,
    float* __restrict__ C, __nv_bfloat16* __restrict__ Ch,
    __nv_bfloat16* __restrict__ Cl,
    int M, int N, int K) {
    extern __shared__ __nv_bfloat16 sm[];
    int tid = threadIdx.x;
    int warp = tid >> 5, lane = tid & 31;
    int wm = warp >> 2, wn = warp & 3;
    int by = blockIdx.y * 128, bx = blockIdx.x * 128;

    float acc[4][4][4];
#pragma unroll
    for (int i = 0; i < 4; i++)
#pragma unroll
        for (int j = 0; j < 4; j++)
#pragma unroll
            for (int f = 0; f < 4; f++) acc[i][j][f] = 0.f;

    issue_tile(sm, Ahg, Alg, Bhg, Blg, 0, K, N, by, bx, tid);
    CP_COMMIT;

    int nt = K >> 5;
    for (int i = 0; i < nt; i++) {
        __nv_bfloat16* cur = sm + (i & 1) * STG;
        if (i + 1 < nt) {
            issue_tile(sm + ((i + 1) & 1) * STG, Ahg, Alg, Bhg, Blg,
                       (i + 1) * 32, K, N, by, bx, tid);
            CP_COMMIT;
            CP_WAIT(1);
        } else {
            CP_WAIT(0);
        }
        __syncthreads();

        const __nv_bfloat16* sAh = cur;
        const __nv_bfloat16* sAl = cur + 5120;
        const __nv_bfloat16* sBh = cur + 10240;
        const __nv_bfloat16* sBl = cur + 14592;
#pragma unroll
        for (int ks = 0; ks < 32; ks += 16) {
            unsigned ah[4][4], al[4][4];
#pragma unroll
            for (int mi = 0; mi < 4; mi++) {
                int row = wm * 64 + mi * 16 + (lane & 15);
                int ce = ks + (lane >> 4) * 8;
                ldsm4(ah[mi], sptr(sAh + row * 40 + ce));
                ldsm4(al[mi], sptr(sAl + row * 40 + ce));
            }
#pragma unroll
            for (int ni = 0; ni < 4; ni++) {
                unsigned bh[2], bl[2];
                int kr = ks + (lane & 15);
                int col = wn * 32 + ni * 8;
                ldsm2t(bh, sptr(sBh + kr * 136 + col));
                ldsm2t(bl, sptr(sBl + kr * 136 + col));
#pragma unroll
                for (int mi = 0; mi < 4; mi++) {
                    mma16816(acc[mi][ni], ah[mi], bh);
                    mma16816(acc[mi][ni], ah[mi], bl);
                    mma16816(acc[mi][ni], al[mi], bh);
                }
            }
        }
        __syncthreads();
    }

    int r0 = by + wm * 64;
    int c0 = bx + wn * 32;
    int lr = lane >> 2, lc = (lane & 3) * 2;
#pragma unroll
    for (int mi = 0; mi < 4; mi++) {
#pragma unroll
        for (int ni = 0; ni < 4; ni++) {
            int col = c0 + ni * 8 + lc;
            float b0 = bias[col], b1 = bias[col + 1];
            int rA = r0 + mi * 16 + lr, rB = rA + 8;
            float v0 = acc[mi][ni][0] + b0, v1 = acc[mi][ni][1] + b1;
            float v2 = acc[mi][ni][2] + b0, v3 = acc[mi][ni][3] + b1;
            if (EPI == 0) {
                C[(size_t)rA * N + col] = v0; C[(size_t)rA * N + col + 1] = v1;
                C[(size_t)rB * N + col] = v2; C[(size_t)rB * N + col + 1] = v3;
            } else {
                v0 = gelu_exact(v0); v1 = gelu_exact(v1);
                v2 = gelu_exact(v2); v3 = gelu_exact(v3);
                split_store(v0, Ch + (size_t)rA * N + col,     Cl + (size_t)rA * N + col);
                split_store(v1, Ch + (size_t)rA * N + col + 1, Cl + (size_t)rA * N + col + 1);
                split_store(v2, Ch + (size_t)rB * N + col,     Cl + (size_t)rB * N + col);
                split_store(v3, Ch + (size_t)rB * N + col + 1, Cl + (size_t)rB * N + col + 1);
            }
        }
    }
}

// ---------------- fused flash attention ----------------
// One block: 64 q rows of one (b,h). 128 threads = 4 warps, 16 q rows/warp.
__global__ __launch_bounds__(128) void k_flash(
    const float* __restrict__ q, const float* __restrict__ k,
    const float* __restrict__ v, const int* __restrict__ mask,
    __nv_bfloat16* __restrict__ oh, __nv_bfloat16* __restrict__ ol) {
    __shared__ __align__(16) char smraw[36864];
    __nv_bfloat16 (*Qh)[72] = (__nv_bfloat16(*)[72])(smraw);
    __nv_bfloat16 (*Ql)[72] = (__nv_bfloat16(*)[72])(smraw + 9216);
    __nv_bfloat16 (*Kh)[72] = (__nv_bfloat16(*)[72])(smraw);
    __nv_bfloat16 (*Kl)[72] = (__nv_bfloat16(*)[72])(smraw + 9216);
    __nv_bfloat16 (*Vh)[72] = (__nv_bfloat16(*)[72])(smraw + 18432);
    __nv_bfloat16 (*Vl)[72] = (__nv_bfloat16(*)[72])(smraw + 27648);
    __shared__ float madd[Ss];

    int bh = blockIdx.y;
    int b = bh >> 4, h = bh & 15;
    int q0 = blockIdx.x * 64;
    int tid = threadIdx.x, warp = tid >> 5, lane = tid & 31;
    int g = lane >> 2, t = lane & 3;

    const float* qb = q + ((size_t)(b * Ss + q0)) * Ee + h * Dd;
    const float* kb = k + ((size_t)(b * Ss)) * Ee + h * Dd;
    const float* vb = v + ((size_t)(b * Ss)) * Ee + h * Dd;

    for (int i = tid; i < Ss; i += 128)
        madd[i] = mask[b * Ss + i] ? 0.f : -1e30f;

#pragma unroll
    for (int l0 = 0; l0 < 8; l0++) {
        int idx = tid + l0 * 128;
        int r = idx >> 4, c = (idx & 15) * 4;
        float4 vq = *(const float4*)(qb + (size_t)r * Ee + c);
        split_store(vq.x, &Qh[r][c + 0], &Ql[r][c + 0]);
        split_store(vq.y, &Qh[r][c + 1], &Ql[r][c + 1]);
        split_store(vq.z, &Qh[r][c + 2], &Ql[r][c + 2]);
        split_store(vq.w, &Qh[r][c + 3], &Ql[r][c + 3]);
    }
    __syncthreads();

    unsigned qfh[4][4], qfl[4][4];
#pragma unroll
    for (int ks = 0; ks < 4; ks++) {
        int row = warp * 16 + (lane & 15);
        int ce = ks * 16 + (lane >> 4) * 8;
        ldsm4(qfh[ks], sptr(&Qh[row][ce]));
        ldsm4(qfl[ks], sptr(&Ql[row][ce]));
    }
    __syncthreads();

    float oacc[8][4];
#pragma unroll
    for (int i = 0; i < 8; i++)
#pragma unroll
        for (int f = 0; f < 4; f++) oacc[i][f] = 0.f;
    float m0 = -INFINITY, m1 = -INFINITY;
    float l0s = 0.f, l1s = 0.f;

    for (int kt = 0; kt < Ss; kt += 64) {
#pragma unroll
        for (int l0 = 0; l0 < 8; l0++) {
            int idx = tid + l0 * 128;
            int r = idx >> 4, c = (idx & 15) * 4;
            float4 vk = *(const float4*)(kb + (size_t)(kt + r) * Ee + c);
            split_store(vk.x, &Kh[r][c + 0], &Kl[r][c + 0]);
            split_store(vk.y, &Kh[r][c + 1], &Kl[r][c + 1]);
            split_store(vk.z, &Kh[r][c + 2], &Kl[r][c + 2]);
            split_store(vk.w, &Kh[r][c + 3], &Kl[r][c + 3]);
            float4 vv = *(const float4*)(vb + (size_t)(kt + r) * Ee + c);
            split_store(vv.x, &Vh[r][c + 0], &Vl[r][c + 0]);
            split_store(vv.y, &Vh[r][c + 1], &Vl[r][c + 1]);
            split_store(vv.z, &Vh[r][c + 2], &Vl[r][c + 2]);
            split_store(vv.w, &Vh[r][c + 3], &Vl[r][c + 3]);
        }
        __syncthreads();

        float sacc[8][4];
#pragma unroll
        for (int i = 0; i < 8; i++)
#pragma unroll
            for (int f = 0; f < 4; f++) sacc[i][f] = 0.f;
#pragma unroll
        for (int ks = 0; ks < 4; ks++) {
#pragma unroll
            for (int ni = 0; ni < 8; ni++) {
                unsigned bh2[2], bl2[2];
                int row = ni * 8 + (lane & 7);
                int ce = ks * 16 + ((lane >> 3) & 1) * 8;
                ldsm2(bh2, sptr(&Kh[row][ce]));
                ldsm2(bl2, sptr(&Kl[row][ce]));
                mma16816(sacc[ni], qfh[ks], bh2);
                mma16816(sacc[ni], qfh[ks], bl2);
                mma16816(sacc[ni], qfl[ks], bh2);
            }
        }

        const float scale = 0.125f;
        float mc0 = -INFINITY, mc1 = -INFINITY;
#pragma unroll
        for (int ni = 0; ni < 8; ni++) {
            int col = kt + ni * 8 + 2 * t;
            float ma = madd[col], mb = madd[col + 1];
            float s0 = sacc[ni][0] * scale + ma;
            float s1 = sacc[ni][1] * scale + mb;
            float s2 = sacc[ni][2] * scale + ma;
            float s3 = sacc[ni][3] * scale + mb;
            sacc[ni][0] = s0; sacc[ni][1] = s1;
            sacc[ni][2] = s2; sacc[ni][3] = s3;
            mc0 = fmaxf(mc0, fmaxf(s0, s1));
            mc1 = fmaxf(mc1, fmaxf(s2, s3));
        }
        mc0 = fmaxf(mc0, __shfl_xor_sync(0xffffffffu, mc0, 1));
        mc0 = fmaxf(mc0, __shfl_xor_sync(0xffffffffu, mc0, 2));
        mc1 = fmaxf(mc1, __shfl_xor_sync(0xffffffffu, mc1, 1));
        mc1 = fmaxf(mc1, __shfl_xor_sync(0xffffffffu, mc1, 2));
        float mn0 = fmaxf(m0, mc0), mn1 = fmaxf(m1, mc1);
        float alpha0 = __expf(m0 - mn0), alpha1 = __expf(m1 - mn1);

        float sum0 = 0.f, sum1 = 0.f;
#pragma unroll
        for (int ni = 0; ni < 8; ni++) {
            float p0 = __expf(sacc[ni][0] - mn0);
            float p1 = __expf(sacc[ni][1] - mn0);
            float p2 = __expf(sacc[ni][2] - mn1);
            float p3 = __expf(sacc[ni][3] - mn1);
            sacc[ni][0] = p0; sacc[ni][1] = p1;
            sacc[ni][2] = p2; sacc[ni][3] = p3;
            sum0 += p0 + p1; sum1 += p2 + p3;
        }
        sum0 += __shfl_xor_sync(0xffffffffu, sum0, 1);
        sum0 += __shfl_xor_sync(0xffffffffu, sum0, 2);
        sum1 += __shfl_xor_sync(0xffffffffu, sum1, 1);
        sum1 += __shfl_xor_sync(0xffffffffu, sum1, 2);
        l0s = l0s * alpha0 + sum0;
        l1s = l1s * alpha1 + sum1;
        m0 = mn0; m1 = mn1;

#pragma unroll
        for (int ni = 0; ni < 8; ni++) {
            oacc[ni][0] *= alpha0; oacc[ni][1] *= alpha0;
            oacc[ni][2] *= alpha1; oacc[ni][3] *= alpha1;
        }

#pragma unroll
        for (int j = 0; j < 4; j++) {
            unsigned pah[4], pal[4];
            {
                float p0 = sacc[2 * j][0], p1 = sacc[2 * j][1];
                float p2 = sacc[2 * j][2], p3 = sacc[2 * j][3];
                float p4 = sacc[2 * j + 1][0], p5 = sacc[2 * j + 1][1];
                float p6 = sacc[2 * j + 1][2], p7 = sacc[2 * j + 1][3];
                __nv_bfloat16 h0 = __float2bfloat16(p0), h1 = __float2bfloat16(p1);
                __nv_bfloat16 h2 = __float2bfloat16(p2), h3 = __float2bfloat16(p3);
                __nv_bfloat16 h4 = __float2bfloat16(p4), h5 = __float2bfloat16(p5);
                __nv_bfloat16 h6 = __float2bfloat16(p6), h7 = __float2bfloat16(p7);
                pah[0] = pack2(h0, h1); pah[1] = pack2(h2, h3);
                pah[2] = pack2(h4, h5); pah[3] = pack2(h6, h7);
                pal[0] = pack2(__float2bfloat16(p0 - __bfloat162float(h0)),
                               __float2bfloat16(p1 - __bfloat162float(h1)));
                pal[1] = pack2(__float2bfloat16(p2 - __bfloat162float(h2)),
                               __float2bfloat16(p3 - __bfloat162float(h3)));
                pal[2] = pack2(__float2bfloat16(p4 - __bfloat162float(h4)),
                               __float2bfloat16(p5 - __bfloat162float(h5)));
                pal[3] = pack2(__float2bfloat16(p6 - __bfloat162float(h6)),
                               __float2bfloat16(p7 - __bfloat162float(h7)));
            }
#pragma unroll
            for (int ni = 0; ni < 8; ni++) {
                unsigned vh2[2], vl2[2];
                int kr = j * 16 + (lane & 15);
                ldsm2t(vh2, sptr(&Vh[kr][ni * 8]));
                ldsm2t(vl2, sptr(&Vl[kr][ni * 8]));
                mma16816(oacc[ni], pah, vh2);
                mma16816(oacc[ni], pal, vh2);
                mma16816(oacc[ni], pah, vl2);
            }
        }
        __syncthreads();
    }

    float inv0 = 1.0f / l0s, inv1 = 1.0f / l1s;
    int r0 = q0 + warp * 16 + g, r1 = r0 + 8;
#pragma unroll
    for (int ni = 0; ni < 8; ni++) {
        int col = h * Dd + ni * 8 + 2 * t;
        size_t oA = ((size_t)(b * Ss + r0)) * Ee + col;
        size_t oB = ((size_t)(b * Ss + r1)) * Ee + col;
        split_store(oacc[ni][0] * inv0, oh + oA,     ol + oA);
        split_store(oacc[ni][1] * inv0, oh + oA + 1, ol + oA + 1);
        split_store(oacc[ni][2] * inv1, oh + oB,     ol + oB);
        split_store(oacc[ni][3] * inv1, oh + oB + 1, ol + oB + 1);
    }
}

// ---------------- residual + layernorm -> bf16 hi/lo ----------------
__global__ void k_ln(const float* __restrict__ wo_out,
                     const float* __restrict__ x,
                     const float* __restrict__ g,
                     const float* __restrict__ be,
                     __nv_bfloat16* __restrict__ outh,
                     __nv_bfloat16* __restrict__ outl) {
    __shared__ float red[256];
    __shared__ float s_mu, s_rstd;
    int t = blockIdx.x;
    int tid = threadIdx.x;
    const float* pa = wo_out + (size_t)t * Ee;
    const float* px = x + (size_t)t * Ee;
    float loc[4];
    float sum = 0.f;
#pragma unroll
    for (int i = 0; i < 4; i++) {
        int idx = i * 256 + tid;
        float vv = pa[idx] + px[idx];
        loc[i] = vv;
        sum += vv;
    }
    red[tid] = sum; __syncthreads();
    for (int s = 128; s > 0; s >>= 1) {
        if (tid < s) red[tid] += red[tid + s];
        __syncthreads();
    }
    if (tid == 0) s_mu = red[0] * (1.0f / Ee);
    __syncthreads();
    float mu = s_mu;
    float vs = 0.f;
#pragma unroll
    for (int i = 0; i < 4; i++) {
        float d = loc[i] - mu;
        vs += d * d;
    }
    red[tid] = vs; __syncthreads();
    for (int s = 128; s > 0; s >>= 1) {
        if (tid < s) red[tid] += red[tid + s];
        __syncthreads();
    }
    if (tid == 0) s_rstd = rsqrtf(red[0] * (1.0f / Ee) + 1e-5f);
    __syncthreads();
    float rstd = s_rstd;
#pragma unroll
    for (int i = 0; i < 4; i++) {
        int idx = i * 256 + tid;
        float o = (loc[i] - mu) * rstd * g[idx] + be[idx];
        split_store(o, outh + (size_t)t * Ee + idx, outl + (size_t)t * Ee + idx);
    }
}

// ---------------- partial column sums of ff2 ----------------
__global__ void k_pmean(const float* __restrict__ f2, float* __restrict__ part) {
    int e = blockIdx.x * 256 + threadIdx.x;
    int b = blockIdx.y;
    int p = blockIdx.z;
    float s = 0.f;
    int s0 = p * 32;
    for (int i = 0; i < 32; i++)
        s += f2[((size_t)(b * Ss + s0 + i)) * Ee + e];
    part[((size_t)p * Bb + b) * Ee + e] = s;
}

// ---------------- final ----------------
__global__ void k_final(const float* __restrict__ part,
                        const float* __restrict__ Wp,
                        const float* __restrict__ bp,
                        float* __restrict__ out) {
    int w = threadIdx.x >> 5;
    int lane = threadIdx.x & 31;
    if (w >= 12) return;
    int b = w / 3, j = w % 3;
    float acc = 0.f;
    for (int e = lane; e < Ee; e += 32) {
        float s = 0.f;
#pragma unroll
        for (int p = 0; p < 64; p++)
            s += part[((size_t)p * Bb + b) * Ee + e];
        acc += s * Wp[e * 3 + j];
    }
#pragma unroll
    for (int o = 16; o > 0; o >>= 1)
        acc += __shfl_down_sync(0xffffffff, acc, o);
    if (lane == 0) out[b * 3 + j] = acc * (1.0f / Ss) + bp[j];
}

// ---------------- launch ----------------
extern "C" void kernel_launch(void* const* d_in, const int* in_sizes, int n_in,
                              void* d_out, int out_size) {
    const int*   ids  = (const int*)d_in[0];
    const int*   mask = (const int*)d_in[1];
    const float* emb  = (const float*)d_in[2];
    const float* Wq = (const float*)d_in[3],  *bq = (const float*)d_in[4];
    const float* Wk = (const float*)d_in[5],  *bk = (const float*)d_in[6];
    const float* Wv = (const float*)d_in[7],  *bv = (const float*)d_in[8];
    const float* Wo = (const float*)d_in[9],  *bo = (const float*)d_in[10];
    const float* lg = (const float*)d_in[11], *lb = (const float*)d_in[12];
    const float* W1 = (const float*)d_in[13], *b1 = (const float*)d_in[14];
    const float* W2 = (const float*)d_in[15], *b2 = (const float*)d_in[16];
    const float* Wp = (const float*)d_in[17], *bp = (const float*)d_in[18];

    float *x, *q, *k, *v, *wo, *f2, *pt;
    __nv_bfloat16 *xh, *xl, *ath, *atl, *hh, *hl, *f1h, *f1l;
    __nv_bfloat16 *wqh, *wql, *wkh, *wkl, *wvh, *wvl, *woh, *wol;
    __nv_bfloat16 *w1h, *w1l, *w2h, *w2l;
    cudaGetSymbolAddress((void**)&x,   g_x);
    cudaGetSymbolAddress((void**)&xh,  g_xh);
    cudaGetSymbolAddress((void**)&xl,  g_xl);
    cudaGetSymbolAddress((void**)&q,   g_q);
    cudaGetSymbolAddress((void**)&k,   g_k);
    cudaGetSymbolAddress((void**)&v,   g_v);
    cudaGetSymbolAddress((void**)&ath, g_ath);
    cudaGetSymbolAddress((void**)&atl, g_atl);
    cudaGetSymbolAddress((void**)&wo,  g_wo);
    cudaGetSymbolAddress((void**)&hh,  g_hh);
    cudaGetSymbolAddress((void**)&hl,  g_hl);
    cudaGetSymbolAddress((void**)&f1h, g_f1h);
    cudaGetSymbolAddress((void**)&f1l, g_f1l);
    cudaGetSymbolAddress((void**)&f2,  g_f2);
    cudaGetSymbolAddress((void**)&pt,  g_pt);
    cudaGetSymbolAddress((void**)&wqh, g_wqh); cudaGetSymbolAddress((void**)&wql, g_wql);
    cudaGetSymbolAddress((void**)&wkh, g_wkh); cudaGetSymbolAddress((void**)&wkl, g_wkl);
    cudaGetSymbolAddress((void**)&wvh, g_wvh); cudaGetSymbolAddress((void**)&wvl, g_wvl);
    cudaGetSymbolAddress((void**)&woh, g_woh); cudaGetSymbolAddress((void**)&wol, g_wol);
    cudaGetSymbolAddress((void**)&w1h, g_w1h); cudaGetSymbolAddress((void**)&w1l, g_w1l);
    cudaGetSymbolAddress((void**)&w2h, g_w2h); cudaGetSymbolAddress((void**)&w2l, g_w2l);

    cudaFuncSetAttribute(k_bgemm<0>, cudaFuncAttributeMaxDynamicSharedMemorySize, SMEM_BYTES);
    cudaFuncSetAttribute(k_bgemm<1>, cudaFuncAttributeMaxDynamicSharedMemorySize, SMEM_BYTES);

    // weight splits
    k_split<<<(Ee * Ee) / 1024, 256>>>(Wq, wqh, wql, Ee * Ee);
    k_split<<<(Ee * Ee) / 1024, 256>>>(Wk, wkh, wkl, Ee * Ee);
    k_split<<<(Ee * Ee) / 1024, 256>>>(Wv, wvh, wvl, Ee * Ee);
    k_split<<<(Ee * Ee) / 1024, 256>>>(Wo, woh, wol, Ee * Ee);
    k_split<<<(Ee * Ff) / 1024, 256>>>(W1, w1h, w1l, Ee * Ff);
    k_split<<<(Ff * Ee) / 1024, 256>>>(W2, w2h, w2l, Ff * Ee);

    k_embed<<<BS, 256>>>(ids, emb, x, xh, xl);

    k_bgemm<0><<<dim3(Ee / 128, BS / 128), 256, SMEM_BYTES>>>(
        xh, xl, wqh, wql, bq, q, nullptr, nullptr, BS, Ee, Ee);
    k_bgemm<0><<<dim3(Ee / 128, BS / 128), 256, SMEM_BYTES>>>(
        xh, xl, wkh, wkl, bk, k, nullptr, nullptr, BS, Ee, Ee);
    k_bgemm<0><<<dim3(Ee / 128, BS / 128), 256, SMEM_BYTES>>>(
        xh, xl, wvh, wvl, bv, v, nullptr, nullptr, BS, Ee, Ee);

    k_flash<<<dim3(Ss / 64, BH), 128>>>(q, k, v, mask, ath, atl);

    k_bgemm<0><<<dim3(Ee / 128, BS / 128), 256, SMEM_BYTES>>>(
        ath, atl, woh, wol, bo, wo, nullptr, nullptr, BS, Ee, Ee);
    k_ln<<<BS, 256>>>(wo, x, lg, lb, hh, hl);

    k_bgemm<1><<<dim3(Ff / 128, BS / 128), 256, SMEM_BYTES>>>(
        hh, hl, w1h, w1l, b1, nullptr, f1h, f1l, BS, Ff, Ee);
    k_bgemm<0><<<dim3(Ee / 128, BS / 128), 256, SMEM_BYTES>>>(
        f1h, f1l, w2h, w2l, b2, f2, nullptr, nullptr, BS, Ee, Ff);

    k_pmean<<<dim3(Ee / 256, Bb, 64), 256>>>(f2, pt);
    k_final<<<1, 384>>>(pt, Wp, bp, (float*)d_out);
}

// round 6
// speedup vs baseline: 4.0815x; 1.5269x over previous
#include <cuda_runtime.h>
#include <cuda_bf16.h>
#include <math.h>

// Problem dims
#define Bb 4
#define Ss 2048
#define Ee 1024
#define Hh 16
#define Dd 64
#define Ff 4096
constexpr int BS = Bb * Ss;   // 8192 tokens
constexpr int BH = Bb * Hh;   // 64

// ---------------- scratch (device globals) -----------
__device__ float g_x [BS * Ee];                      // fp32 embeddings (residual)
__device__ __nv_bfloat16 g_xb[BS * Ee];              // bf16 embeddings (GEMM A)
__device__ __nv_bfloat16 g_qb[BS * Ee];
__device__ __nv_bfloat16 g_kb[BS * Ee];
__device__ __nv_bfloat16 g_vb[BS * Ee];
__device__ __nv_bfloat16 g_ab[BS * Ee];              // attention out
__device__ float g_wo[BS * Ee];
__device__ __nv_bfloat16 g_hb[BS * Ee];              // post-LN
__device__ __nv_bfloat16 g_f1b[(size_t)BS * Ff];
__device__ float g_f2[BS * Ee];
__device__ float g_pt[64 * Bb * Ee];
// pre-split weights (hi/lo) — systematic error must be avoided
__device__ __nv_bfloat16 g_wqh[Ee * Ee], g_wql[Ee * Ee];
__device__ __nv_bfloat16 g_wkh[Ee * Ee], g_wkl[Ee * Ee];
__device__ __nv_bfloat16 g_wvh[Ee * Ee], g_wvl[Ee * Ee];
__device__ __nv_bfloat16 g_woh[Ee * Ee], g_wol[Ee * Ee];
__device__ __nv_bfloat16 g_w1h[Ee * Ff], g_w1l[Ee * Ff];
__device__ __nv_bfloat16 g_w2h[Ff * Ee], g_w2l[Ff * Ee];

// ---------------- helpers ----------------
__device__ __forceinline__ unsigned sptr(const void* p) {
    unsigned a;
    asm("{ .reg .u64 t; cvta.to.shared.u64 t, %1; cvt.u32.u64 %0, t; }"
        : "=r"(a) : "l"(p));
    return a;
}
__device__ __forceinline__ void ldsm4(unsigned* r, unsigned a) {
    asm volatile("ldmatrix.sync.aligned.m8n8.x4.shared.b16 {%0,%1,%2,%3}, [%4];"
                 : "=r"(r[0]), "=r"(r[1]), "=r"(r[2]), "=r"(r[3]) : "r"(a));
}
__device__ __forceinline__ void ldsm2(unsigned* r, unsigned a) {
    asm volatile("ldmatrix.sync.aligned.m8n8.x2.shared.b16 {%0,%1}, [%2];"
                 : "=r"(r[0]), "=r"(r[1]) : "r"(a));
}
__device__ __forceinline__ void ldsm2t(unsigned* r, unsigned a) {
    asm volatile("ldmatrix.sync.aligned.m8n8.x2.trans.shared.b16 {%0,%1}, [%2];"
                 : "=r"(r[0]), "=r"(r[1]) : "r"(a));
}
__device__ __forceinline__ void mma16816(float* c, const unsigned* a, const unsigned* b) {
    asm volatile(
        "mma.sync.aligned.m16n8k16.row.col.f32.bf16.bf16.f32 "
        "{%0,%1,%2,%3}, {%4,%5,%6,%7}, {%8,%9}, {%0,%1,%2,%3};"
        : "+f"(c[0]), "+f"(c[1]), "+f"(c[2]), "+f"(c[3])
        : "r"(a[0]), "r"(a[1]), "r"(a[2]), "r"(a[3]), "r"(b[0]), "r"(b[1]));
}
__device__ __forceinline__ void cpa16(unsigned dst, const void* src) {
    asm volatile("cp.async.cg.shared.global [%0], [%1], 16;"
                 :: "r"(dst), "l"(src));
}
#define CP_COMMIT asm volatile("cp.async.commit_group;" ::: "memory")
#define CP_WAIT(n) asm volatile("cp.async.wait_group %0;" :: "n"(n) : "memory")

__device__ __forceinline__ void split_store(float v, __nv_bfloat16* hi, __nv_bfloat16* lo) {
    __nv_bfloat16 h = __float2bfloat16(v);
    *hi = h;
    *lo = __float2bfloat16(v - __bfloat162float(h));
}
__device__ __forceinline__ unsigned pack2(__nv_bfloat16 a, __nv_bfloat16 b) {
    unsigned short ua = *(unsigned short*)&a, ub = *(unsigned short*)&b;
    return (unsigned)ua | ((unsigned)ub << 16);
}
__device__ __forceinline__ float gelu_exact(float t) {
    return 0.5f * t * (1.0f + erff(t * 0.70710678118654752f));
}

// ---------------- fp32 -> bf16 hi/lo split (weights) ----------------
__global__ void k_split(const float* __restrict__ in,
                        __nv_bfloat16* __restrict__ hi,
                        __nv_bfloat16* __restrict__ lo, int n) {
    int i = (blockIdx.x * 256 + threadIdx.x) * 4;
    if (i >= n) return;
    float4 v = *(const float4*)(in + i);
    __nv_bfloat16 hs[4], ls[4];
    split_store(v.x, &hs[0], &ls[0]);
    split_store(v.y, &hs[1], &ls[1]);
    split_store(v.z, &hs[2], &ls[2]);
    split_store(v.w, &hs[3], &ls[3]);
    *(uint2*)(hi + i) = *(uint2*)hs;
    *(uint2*)(lo + i) = *(uint2*)ls;
}

// ---------------- embedding gather ----------------
__global__ void k_embed(const int* __restrict__ ids,
                        const float* __restrict__ emb,
                        float* __restrict__ x,
                        __nv_bfloat16* __restrict__ xb) {
    int t = blockIdx.x;
    int id = ids[t];
    size_t off = (size_t)t * Ee + threadIdx.x * 4;
    float4 v = *(const float4*)(emb + (size_t)id * Ee + threadIdx.x * 4);
    *(float4*)(x + off) = v;
    __nv_bfloat16 hs[4];
    hs[0] = __float2bfloat16(v.x); hs[1] = __float2bfloat16(v.y);
    hs[2] = __float2bfloat16(v.z); hs[3] = __float2bfloat16(v.w);
    *(uint2*)(xb + off) = *(uint2*)hs;
}

// ---------------- GEMM: A bf16 plain, B hi/lo; 3-stage cp.async ----------
// BM=128 BN=128 BK=32. 256 threads = 8 warps (2m x 4n), warp tile 64x32.
// stage elems: A[128*40]@0, Bh[32*136]@5120, Bl@9472 ; STG=13824 elems
constexpr int GSTG = 13824;
constexpr int GSM_BYTES = 3 * GSTG * 2;   // 82944

__device__ __forceinline__ void g_issue(
    __nv_bfloat16* st,
    const __nv_bfloat16* __restrict__ Ab,
    const __nv_bfloat16* __restrict__ Bhg, const __nv_bfloat16* __restrict__ Blg,
    int k0, int K, int N, int by, int bx, int tid) {
#pragma unroll
    for (int l = 0; l < 2; l++) {
        int cid = tid + l * 256;
        int r = cid >> 2, c8 = (cid & 3) * 8;
        cpa16(sptr(st + r * 40 + c8), Ab + (size_t)(by + r) * K + k0 + c8);
        int rb = cid >> 4, cb = (cid & 15) * 8;
        cpa16(sptr(st + 5120 + rb * 136 + cb), Bhg + (size_t)(k0 + rb) * N + bx + cb);
        cpa16(sptr(st + 9472 + rb * 136 + cb), Blg + (size_t)(k0 + rb) * N + bx + cb);
    }
}

template <int EPI>  // 0: fp32 out  1: bf16 out  2: gelu -> bf16 out
__global__ __launch_bounds__(256, 2) void k_bgemm(
    const __nv_bfloat16* __restrict__ Ab,
    const __nv_bfloat16* __restrict__ Bhg, const __nv_bfloat16* __restrict__ Blg,
    const float* __restrict__ bias,
    float* __restrict__ Cf, __nv_bfloat16* __restrict__ Cb,
    int M, int N, int K) {
    extern __shared__ __nv_bfloat16 sm[];
    int tid = threadIdx.x;
    int warp = tid >> 5, lane = tid & 31;
    int wm = warp >> 2, wn = warp & 3;
    int by = blockIdx.y * 128, bx = blockIdx.x * 128;

    float acc[4][4][4];
#pragma unroll
    for (int i = 0; i < 4; i++)
#pragma unroll
        for (int j = 0; j < 4; j++)
#pragma unroll
            for (int f = 0; f < 4; f++) acc[i][j][f] = 0.f;

    int nt = K >> 5;
    g_issue(sm, Ab, Bhg, Blg, 0, K, N, by, bx, tid);
    CP_COMMIT;
    g_issue(sm + GSTG, Ab, Bhg, Blg, 32, K, N, by, bx, tid);
    CP_COMMIT;

    for (int i = 0; i < nt; i++) {
        if (i + 1 < nt) { CP_WAIT(1); } else { CP_WAIT(0); }
        __syncthreads();
        __nv_bfloat16* cur = sm + (i % 3) * GSTG;
        const __nv_bfloat16* sA  = cur;
        const __nv_bfloat16* sBh = cur + 5120;
        const __nv_bfloat16* sBl = cur + 9472;
#pragma unroll
        for (int ks = 0; ks < 32; ks += 16) {
            unsigned ah[4][4];
#pragma unroll
            for (int mi = 0; mi < 4; mi++) {
                int row = wm * 64 + mi * 16 + (lane & 15);
                int ce = ks + (lane >> 4) * 8;
                ldsm4(ah[mi], sptr(sA + row * 40 + ce));
            }
#pragma unroll
            for (int ni = 0; ni < 4; ni++) {
                unsigned bh[2], bl[2];
                int kr = ks + (lane & 15);
                int col = wn * 32 + ni * 8;
                ldsm2t(bh, sptr(sBh + kr * 136 + col));
                ldsm2t(bl, sptr(sBl + kr * 136 + col));
#pragma unroll
                for (int mi = 0; mi < 4; mi++) {
                    mma16816(acc[mi][ni], ah[mi], bh);
                    mma16816(acc[mi][ni], ah[mi], bl);
                }
            }
        }
        __syncthreads();
        if (i + 2 < nt) {
            g_issue(sm + ((i + 2) % 3) * GSTG, Ab, Bhg, Blg,
                    (i + 2) * 32, K, N, by, bx, tid);
            CP_COMMIT;
        }
    }

    int r0 = by + wm * 64;
    int c0 = bx + wn * 32;
    int lr = lane >> 2, lc = (lane & 3) * 2;
#pragma unroll
    for (int mi = 0; mi < 4; mi++) {
#pragma unroll
        for (int ni = 0; ni < 4; ni++) {
            int col = c0 + ni * 8 + lc;
            float b0 = bias[col], b1 = bias[col + 1];
            int rA = r0 + mi * 16 + lr, rB = rA + 8;
            float v0 = acc[mi][ni][0] + b0, v1 = acc[mi][ni][1] + b1;
            float v2 = acc[mi][ni][2] + b0, v3 = acc[mi][ni][3] + b1;
            if (EPI == 2) {
                v0 = gelu_exact(v0); v1 = gelu_exact(v1);
                v2 = gelu_exact(v2); v3 = gelu_exact(v3);
            }
            if (EPI == 0) {
                Cf[(size_t)rA * N + col] = v0; Cf[(size_t)rA * N + col + 1] = v1;
                Cf[(size_t)rB * N + col] = v2; Cf[(size_t)rB * N + col + 1] = v3;
            } else {
                Cb[(size_t)rA * N + col]     = __float2bfloat16(v0);
                Cb[(size_t)rA * N + col + 1] = __float2bfloat16(v1);
                Cb[(size_t)rB * N + col]     = __float2bfloat16(v2);
                Cb[(size_t)rB * N + col + 1] = __float2bfloat16(v3);
            }
        }
    }
}

// ---------------- fused flash attention (plain bf16, 2-stage cp.async) ------
// One block: 64 q rows of one (b,h). 128 threads = 4 warps, 16 q rows/warp.
// dyn smem: QB@0 (9216B), stage s @ 9216+s*18432 {K@0, V@9216}, madd @46080
constexpr int FSM_BYTES = 46080 + 8192;   // 54272

__global__ __launch_bounds__(128) void k_flash(
    const __nv_bfloat16* __restrict__ q, const __nv_bfloat16* __restrict__ k,
    const __nv_bfloat16* __restrict__ v, const int* __restrict__ mask,
    __nv_bfloat16* __restrict__ o) {
    extern __shared__ __align__(16) char fsm[];
    __nv_bfloat16* QB = (__nv_bfloat16*)fsm;
    float* madd = (float*)(fsm + 46080);

    int bh = blockIdx.y;
    int b = bh >> 4, h = bh & 15;
    int q0 = blockIdx.x * 64;
    int tid = threadIdx.x, warp = tid >> 5, lane = tid & 31;
    int g = lane >> 2, t = lane & 3;

    const __nv_bfloat16* qg = q + ((size_t)(b * Ss + q0)) * Ee + h * Dd;
    const __nv_bfloat16* kg = k + ((size_t)(b * Ss)) * Ee + h * Dd;
    const __nv_bfloat16* vg = v + ((size_t)(b * Ss)) * Ee + h * Dd;

    // Q tile (64x64) via cp.async — group 0
#pragma unroll
    for (int l = 0; l < 4; l++) {
        int cid = tid + l * 128;
        int r = cid >> 3, c8 = (cid & 7) * 8;
        cpa16(sptr(QB + r * 72 + c8), qg + (size_t)r * Ee + c8);
    }
    CP_COMMIT;

    // kv tile 0 — group 1
    {
        __nv_bfloat16* st = (__nv_bfloat16*)(fsm + 9216);
#pragma unroll
        for (int l = 0; l < 4; l++) {
            int cid = tid + l * 128;
            int r = cid >> 3, c8 = (cid & 7) * 8;
            cpa16(sptr(st + r * 72 + c8), kg + (size_t)r * Ee + c8);
            cpa16(sptr(st + 4608 + r * 72 + c8), vg + (size_t)r * Ee + c8);
        }
        CP_COMMIT;
    }

    for (int i = tid; i < Ss; i += 128)
        madd[i] = mask[b * Ss + i] ? 0.f : -1e30f;

    CP_WAIT(1);   // Q ready
    __syncthreads();
    unsigned qf[4][4];
#pragma unroll
    for (int ks = 0; ks < 4; ks++) {
        int row = warp * 16 + (lane & 15);
        int ce = ks * 16 + (lane >> 4) * 8;
        ldsm4(qf[ks], sptr(QB + row * 72 + ce));
    }

    float oacc[8][4];
#pragma unroll
    for (int i = 0; i < 8; i++)
#pragma unroll
        for (int f = 0; f < 4; f++) oacc[i][f] = 0.f;
    float m0 = -INFINITY, m1 = -INFINITY;
    float l0s = 0.f, l1s = 0.f;

    constexpr int NT = Ss / 64;   // 32 tiles
    for (int ti = 0; ti < NT; ti++) {
        if (ti + 1 < NT) {
            __nv_bfloat16* st = (__nv_bfloat16*)(fsm + 9216 + ((ti + 1) & 1) * 18432);
            int kt = (ti + 1) * 64;
#pragma unroll
            for (int l = 0; l < 4; l++) {
                int cid = tid + l * 128;
                int r = cid >> 3, c8 = (cid & 7) * 8;
                cpa16(sptr(st + r * 72 + c8), kg + (size_t)(kt + r) * Ee + c8);
                cpa16(sptr(st + 4608 + r * 72 + c8), vg + (size_t)(kt + r) * Ee + c8);
            }
            CP_COMMIT;
            CP_WAIT(1);
        } else {
            CP_WAIT(0);
        }
        __syncthreads();
        const __nv_bfloat16* Kt = (const __nv_bfloat16*)(fsm + 9216 + (ti & 1) * 18432);
        const __nv_bfloat16* Vt = Kt + 4608;
        int kt = ti * 64;

        // S = Q K^T
        float sacc[8][4];
#pragma unroll
        for (int i = 0; i < 8; i++)
#pragma unroll
            for (int f = 0; f < 4; f++) sacc[i][f] = 0.f;
#pragma unroll
        for (int ks = 0; ks < 4; ks++) {
#pragma unroll
            for (int ni = 0; ni < 8; ni++) {
                unsigned kb2[2];
                int row = ni * 8 + (lane & 7);
                int ce = ks * 16 + ((lane >> 3) & 1) * 8;
                ldsm2(kb2, sptr(Kt + row * 72 + ce));
                mma16816(sacc[ni], qf[ks], kb2);
            }
        }

        const float scale = 0.125f;
        float mc0 = -INFINITY, mc1 = -INFINITY;
#pragma unroll
        for (int ni = 0; ni < 8; ni++) {
            int col = kt + ni * 8 + 2 * t;
            float ma = madd[col], mb = madd[col + 1];
            float s0 = sacc[ni][0] * scale + ma;
            float s1 = sacc[ni][1] * scale + mb;
            float s2 = sacc[ni][2] * scale + ma;
            float s3 = sacc[ni][3] * scale + mb;
            sacc[ni][0] = s0; sacc[ni][1] = s1;
            sacc[ni][2] = s2; sacc[ni][3] = s3;
            mc0 = fmaxf(mc0, fmaxf(s0, s1));
            mc1 = fmaxf(mc1, fmaxf(s2, s3));
        }
        mc0 = fmaxf(mc0, __shfl_xor_sync(0xffffffffu, mc0, 1));
        mc0 = fmaxf(mc0, __shfl_xor_sync(0xffffffffu, mc0, 2));
        mc1 = fmaxf(mc1, __shfl_xor_sync(0xffffffffu, mc1, 1));
        mc1 = fmaxf(mc1, __shfl_xor_sync(0xffffffffu, mc1, 2));
        float mn0 = fmaxf(m0, mc0), mn1 = fmaxf(m1, mc1);
        float alpha0 = __expf(m0 - mn0), alpha1 = __expf(m1 - mn1);

        float sum0 = 0.f, sum1 = 0.f;
#pragma unroll
        for (int ni = 0; ni < 8; ni++) {
            float p0 = __expf(sacc[ni][0] - mn0);
            float p1 = __expf(sacc[ni][1] - mn0);
            float p2 = __expf(sacc[ni][2] - mn1);
            float p3 = __expf(sacc[ni][3] - mn1);
            sacc[ni][0] = p0; sacc[ni][1] = p1;
            sacc[ni][2] = p2; sacc[ni][3] = p3;
            sum0 += p0 + p1; sum1 += p2 + p3;
        }
        sum0 += __shfl_xor_sync(0xffffffffu, sum0, 1);
        sum0 += __shfl_xor_sync(0xffffffffu, sum0, 2);
        sum1 += __shfl_xor_sync(0xffffffffu, sum1, 1);
        sum1 += __shfl_xor_sync(0xffffffffu, sum1, 2);
        l0s = l0s * alpha0 + sum0;
        l1s = l1s * alpha1 + sum1;
        m0 = mn0; m1 = mn1;

#pragma unroll
        for (int ni = 0; ni < 8; ni++) {
            oacc[ni][0] *= alpha0; oacc[ni][1] *= alpha0;
            oacc[ni][2] *= alpha1; oacc[ni][3] *= alpha1;
        }

        // O += P @ V (P plain bf16 from registers)
#pragma unroll
        for (int j = 0; j < 4; j++) {
            unsigned pa[4];
            pa[0] = pack2(__float2bfloat16(sacc[2 * j][0]), __float2bfloat16(sacc[2 * j][1]));
            pa[1] = pack2(__float2bfloat16(sacc[2 * j][2]), __float2bfloat16(sacc[2 * j][3]));
            pa[2] = pack2(__float2bfloat16(sacc[2 * j + 1][0]), __float2bfloat16(sacc[2 * j + 1][1]));
            pa[3] = pack2(__float2bfloat16(sacc[2 * j + 1][2]), __float2bfloat16(sacc[2 * j + 1][3]));
#pragma unroll
            for (int ni = 0; ni < 8; ni++) {
                unsigned vh2[2];
                int kr = j * 16 + (lane & 15);
                ldsm2t(vh2, sptr(Vt + kr * 72 + ni * 8));
                mma16816(oacc[ni], pa, vh2);
            }
        }
        __syncthreads();
    }

    float inv0 = 1.0f / l0s, inv1 = 1.0f / l1s;
    int r0 = q0 + warp * 16 + g, r1 = r0 + 8;
#pragma unroll
    for (int ni = 0; ni < 8; ni++) {
        int col = h * Dd + ni * 8 + 2 * t;
        size_t oA = ((size_t)(b * Ss + r0)) * Ee + col;
        size_t oB = ((size_t)(b * Ss + r1)) * Ee + col;
        o[oA]     = __float2bfloat16(oacc[ni][0] * inv0);
        o[oA + 1] = __float2bfloat16(oacc[ni][1] * inv0);
        o[oB]     = __float2bfloat16(oacc[ni][2] * inv1);
        o[oB + 1] = __float2bfloat16(oacc[ni][3] * inv1);
    }
}

// ---------------- residual + layernorm -> bf16 ----------------
__global__ void k_ln(const float* __restrict__ wo_out,
                     const float* __restrict__ x,
                     const float* __restrict__ g,
                     const float* __restrict__ be,
                     __nv_bfloat16* __restrict__ outb) {
    __shared__ float red[256];
    __shared__ float s_mu, s_rstd;
    int t = blockIdx.x;
    int tid = threadIdx.x;
    const float* pa = wo_out + (size_t)t * Ee;
    const float* px = x + (size_t)t * Ee;
    float loc[4];
    float sum = 0.f;
#pragma unroll
    for (int i = 0; i < 4; i++) {
        int idx = i * 256 + tid;
        float vv = pa[idx] + px[idx];
        loc[i] = vv;
        sum += vv;
    }
    red[tid] = sum; __syncthreads();
    for (int s = 128; s > 0; s >>= 1) {
        if (tid < s) red[tid] += red[tid + s];
        __syncthreads();
    }
    if (tid == 0) s_mu = red[0] * (1.0f / Ee);
    __syncthreads();
    float mu = s_mu;
    float vs = 0.f;
#pragma unroll
    for (int i = 0; i < 4; i++) {
        float d = loc[i] - mu;
        vs += d * d;
    }
    red[tid] = vs; __syncthreads();
    for (int s = 128; s > 0; s >>= 1) {
        if (tid < s) red[tid] += red[tid + s];
        __syncthreads();
    }
    if (tid == 0) s_rstd = rsqrtf(red[0] * (1.0f / Ee) + 1e-5f);
    __syncthreads();
    float rstd = s_rstd;
#pragma unroll
    for (int i = 0; i < 4; i++) {
        int idx = i * 256 + tid;
        float o = (loc[i] - mu) * rstd * g[idx] + be[idx];
        outb[(size_t)t * Ee + idx] = __float2bfloat16(o);
    }
}

// ---------------- partial column sums of ff2 ----------------
__global__ void k_pmean(const float* __restrict__ f2, float* __restrict__ part) {
    int e = blockIdx.x * 256 + threadIdx.x;
    int b = blockIdx.y;
    int p = blockIdx.z;
    float s = 0.f;
    int s0 = p * 32;
    for (int i = 0; i < 32; i++)
        s += f2[((size_t)(b * Ss + s0 + i)) * Ee + e];
    part[((size_t)p * Bb + b) * Ee + e] = s;
}

// ---------------- final ----------------
__global__ void k_final(const float* __restrict__ part,
                        const float* __restrict__ Wp,
                        const float* __restrict__ bp,
                        float* __restrict__ out) {
    int w = threadIdx.x >> 5;
    int lane = threadIdx.x & 31;
    if (w >= 12) return;
    int b = w / 3, j = w % 3;
    float acc = 0.f;
    for (int e = lane; e < Ee; e += 32) {
        float s = 0.f;
#pragma unroll
        for (int p = 0; p < 64; p++)
            s += part[((size_t)p * Bb + b) * Ee + e];
        acc += s * Wp[e * 3 + j];
    }
#pragma unroll
    for (int o = 16; o > 0; o >>= 1)
        acc += __shfl_down_sync(0xffffffff, acc, o);
    if (lane == 0) out[b * 3 + j] = acc * (1.0f / Ss) + bp[j];
}

// ---------------- launch ----------------
extern "C" void kernel_launch(void* const* d_in, const int* in_sizes, int n_in,
                              void* d_out, int out_size) {
    const int*   ids  = (const int*)d_in[0];
    const int*   mask = (const int*)d_in[1];
    const float* emb  = (const float*)d_in[2];
    const float* Wq = (const float*)d_in[3],  *bq = (const float*)d_in[4];
    const float* Wk = (const float*)d_in[5],  *bk = (const float*)d_in[6];
    const float* Wv = (const float*)d_in[7],  *bv = (const float*)d_in[8];
    const float* Wo = (const float*)d_in[9],  *bo = (const float*)d_in[10];
    const float* lg = (const float*)d_in[11], *lb = (const float*)d_in[12];
    const float* W1 = (const float*)d_in[13], *b1 = (const float*)d_in[14];
    const float* W2 = (const float*)d_in[15], *b2 = (const float*)d_in[16];
    const float* Wp = (const float*)d_in[17], *bp = (const float*)d_in[18];

    float *x, *wo, *f2, *pt;
    __nv_bfloat16 *xb, *qb, *kb, *vb, *ab, *hb, *f1b;
    __nv_bfloat16 *wqh, *wql, *wkh, *wkl, *wvh, *wvl, *woh, *wol;
    __nv_bfloat16 *w1h, *w1l, *w2h, *w2l;
    cudaGetSymbolAddress((void**)&x,   g_x);
    cudaGetSymbolAddress((void**)&xb,  g_xb);
    cudaGetSymbolAddress((void**)&qb,  g_qb);
    cudaGetSymbolAddress((void**)&kb,  g_kb);
    cudaGetSymbolAddress((void**)&vb,  g_vb);
    cudaGetSymbolAddress((void**)&ab,  g_ab);
    cudaGetSymbolAddress((void**)&wo,  g_wo);
    cudaGetSymbolAddress((void**)&hb,  g_hb);
    cudaGetSymbolAddress((void**)&f1b, g_f1b);
    cudaGetSymbolAddress((void**)&f2,  g_f2);
    cudaGetSymbolAddress((void**)&pt,  g_pt);
    cudaGetSymbolAddress((void**)&wqh, g_wqh); cudaGetSymbolAddress((void**)&wql, g_wql);
    cudaGetSymbolAddress((void**)&wkh, g_wkh); cudaGetSymbolAddress((void**)&wkl, g_wkl);
    cudaGetSymbolAddress((void**)&wvh, g_wvh); cudaGetSymbolAddress((void**)&wvl, g_wvl);
    cudaGetSymbolAddress((void**)&woh, g_woh); cudaGetSymbolAddress((void**)&wol, g_wol);
    cudaGetSymbolAddress((void**)&w1h, g_w1h); cudaGetSymbolAddress((void**)&w1l, g_w1l);
    cudaGetSymbolAddress((void**)&w2h, g_w2h); cudaGetSymbolAddress((void**)&w2l, g_w2l);

    cudaFuncSetAttribute(k_bgemm<0>, cudaFuncAttributeMaxDynamicSharedMemorySize, GSM_BYTES);
    cudaFuncSetAttribute(k_bgemm<1>, cudaFuncAttributeMaxDynamicSharedMemorySize, GSM_BYTES);
    cudaFuncSetAttribute(k_bgemm<2>, cudaFuncAttributeMaxDynamicSharedMemorySize, GSM_BYTES);
    cudaFuncSetAttribute(k_flash,    cudaFuncAttributeMaxDynamicSharedMemorySize, FSM_BYTES);

    // weight splits
    k_split<<<(Ee * Ee) / 1024, 256>>>(Wq, wqh, wql, Ee * Ee);
    k_split<<<(Ee * Ee) / 1024, 256>>>(Wk, wkh, wkl, Ee * Ee);
    k_split<<<(Ee * Ee) / 1024, 256>>>(Wv, wvh, wvl, Ee * Ee);
    k_split<<<(Ee * Ee) / 1024, 256>>>(Wo, woh, wol, Ee * Ee);
    k_split<<<(Ee * Ff) / 1024, 256>>>(W1, w1h, w1l, Ee * Ff);
    k_split<<<(Ff * Ee) / 1024, 256>>>(W2, w2h, w2l, Ff * Ee);

    k_embed<<<BS, 256>>>(ids, emb, x, xb);

    k_bgemm<1><<<dim3(Ee / 128, BS / 128), 256, GSM_BYTES>>>(
        xb, wqh, wql, bq, nullptr, qb, BS, Ee, Ee);
    k_bgemm<1><<<dim3(Ee / 128, BS / 128), 256, GSM_BYTES>>>(
        xb, wkh, wkl, bk, nullptr, kb, BS, Ee, Ee);
    k_bgemm<1><<<dim3(Ee / 128, BS / 128), 256, GSM_BYTES>>>(
        xb, wvh, wvl, bv, nullptr, vb, BS, Ee, Ee);

    k_flash<<<dim3(Ss / 64, BH), 128, FSM_BYTES>>>(qb, kb, vb, mask, ab);

    k_bgemm<0><<<dim3(Ee / 128, BS / 128), 256, GSM_BYTES>>>(
        ab, woh, wol, bo, wo, nullptr, BS, Ee, Ee);
    k_ln<<<BS, 256>>>(wo, x, lg, lb, hb);

    k_bgemm<2><<<dim3(Ff / 128, BS / 128), 256, GSM_BYTES>>>(
        hb, w1h, w1l, b1, nullptr, f1b, BS, Ff, Ee);
    k_bgemm<0><<<dim3(Ee / 128, BS / 128), 256, GSM_BYTES>>>(
        f1b, w2h, w2l, b2, f2, nullptr, BS, Ee, Ff);

    k_pmean<<<dim3(Ee / 256, Bb, 64), 256>>>(f2, pt);
    k_final<<<1, 384>>>(pt, Wp, bp, (float*)d_out);
}

// round 8
// speedup vs baseline: 5.7111x; 1.3993x over previous
#include <cuda_runtime.h>
#include <cuda_fp16.h>
#include <math.h>

// Problem dims
#define Bb 4
#define Ss 2048
#define Ee 1024
#define Hh 16
#define Dd 64
#define Ff 4096
constexpr int BS = Bb * Ss;   // 8192 tokens
constexpr int BH = Bb * Hh;   // 64

// ---------------- scratch (device globals) -----------
__device__ float g_x [BS * Ee];                      // fp32 embeddings (residual)
__device__ __half g_xb[BS * Ee];                     // fp16 embeddings (GEMM A)
__device__ __half g_qb[BS * Ee];
__device__ __half g_kb[BS * Ee];
__device__ __half g_vb[BS * Ee];
__device__ __half g_ab[BS * Ee];                     // attention out
__device__ float g_wo[BS * Ee];
__device__ __half g_hb[BS * Ee];                     // post-LN
__device__ __half g_f1b[(size_t)BS * Ff];
__device__ float g_f2[BS * Ee];
__device__ float g_pt[64 * Bb * Ee];
// fp16 weights
__device__ __half g_wq[Ee * Ee];
__device__ __half g_wk[Ee * Ee];
__device__ __half g_wv[Ee * Ee];
__device__ __half g_wom[Ee * Ee];
__device__ __half g_w1[(size_t)Ee * Ff];
__device__ __half g_w2[(size_t)Ff * Ee];

// ---------------- helpers ----------------
__device__ __forceinline__ unsigned sptr(const void* p) {
    unsigned a;
    asm("{ .reg .u64 t; cvta.to.shared.u64 t, %1; cvt.u32.u64 %0, t; }"
        : "=r"(a) : "l"(p));
    return a;
}
__device__ __forceinline__ void ldsm4(unsigned* r, unsigned a) {
    asm volatile("ldmatrix.sync.aligned.m8n8.x4.shared.b16 {%0,%1,%2,%3}, [%4];"
                 : "=r"(r[0]), "=r"(r[1]), "=r"(r[2]), "=r"(r[3]) : "r"(a));
}
__device__ __forceinline__ void ldsm2(unsigned* r, unsigned a) {
    asm volatile("ldmatrix.sync.aligned.m8n8.x2.shared.b16 {%0,%1}, [%2];"
                 : "=r"(r[0]), "=r"(r[1]) : "r"(a));
}
__device__ __forceinline__ void ldsm2t(unsigned* r, unsigned a) {
    asm volatile("ldmatrix.sync.aligned.m8n8.x2.trans.shared.b16 {%0,%1}, [%2];"
                 : "=r"(r[0]), "=r"(r[1]) : "r"(a));
}
__device__ __forceinline__ void mma16816h(float* c, const unsigned* a, const unsigned* b) {
    asm volatile(
        "mma.sync.aligned.m16n8k16.row.col.f32.f16.f16.f32 "
        "{%0,%1,%2,%3}, {%4,%5,%6,%7}, {%8,%9}, {%0,%1,%2,%3};"
        : "+f"(c[0]), "+f"(c[1]), "+f"(c[2]), "+f"(c[3])
        : "r"(a[0]), "r"(a[1]), "r"(a[2]), "r"(a[3]), "r"(b[0]), "r"(b[1]));
}
__device__ __forceinline__ void cpa16(unsigned dst, const void* src) {
    asm volatile("cp.async.cg.shared.global [%0], [%1], 16;"
                 :: "r"(dst), "l"(src));
}
#define CP_COMMIT asm volatile("cp.async.commit_group;" ::: "memory")
#define CP_WAIT(n) asm volatile("cp.async.wait_group %0;" :: "n"(n) : "memory")

__device__ __forceinline__ unsigned pack2h(__half a, __half b) {
    unsigned short ua = *(unsigned short*)&a, ub = *(unsigned short*)&b;
    return (unsigned)ua | ((unsigned)ub << 16);
}
__device__ __forceinline__ float gelu_exact(float t) {
    return 0.5f * t * (1.0f + erff(t * 0.70710678118654752f));
}

// ---------------- fp32 -> fp16 convert ----------------
__global__ void k_half(const float* __restrict__ in,
                       __half* __restrict__ out, int n) {
    int i = (blockIdx.x * 256 + threadIdx.x) * 4;
    if (i >= n) return;
    float4 v = *(const float4*)(in + i);
    __half hs[4];
    hs[0] = __float2half_rn(v.x); hs[1] = __float2half_rn(v.y);
    hs[2] = __float2half_rn(v.z); hs[3] = __float2half_rn(v.w);
    *(uint2*)(out + i) = *(uint2*)hs;
}

// ---------------- embedding gather ----------------
__global__ void k_embed(const int* __restrict__ ids,
                        const float* __restrict__ emb,
                        float* __restrict__ x,
                        __half* __restrict__ xb) {
    int t = blockIdx.x;
    int id = ids[t];
    size_t off = (size_t)t * Ee + threadIdx.x * 4;
    float4 v = *(const float4*)(emb + (size_t)id * Ee + threadIdx.x * 4);
    *(float4*)(x + off) = v;
    __half hs[4];
    hs[0] = __float2half_rn(v.x); hs[1] = __float2half_rn(v.y);
    hs[2] = __float2half_rn(v.z); hs[3] = __float2half_rn(v.w);
    *(uint2*)(xb + off) = *(uint2*)hs;
}

// ---------------- fp16 GEMM, 3-stage cp.async ----------
// BM=128 BN=128 BK=32. 256 threads = 8 warps (2m x 4n), warp tile 64x32.
// stage elems (half): A[128*40]@0, B[32*136]@5120 ; GSTG=9472 elems
constexpr int GSTG = 9472;
constexpr int GSM_BYTES = 3 * GSTG * 2;   // 56832

__device__ __forceinline__ void g_issue(
    __half* st,
    const __half* __restrict__ Ab, const __half* __restrict__ Bg,
    int k0, int K, int N, int by, int bx, int tid) {
#pragma unroll
    for (int l = 0; l < 2; l++) {
        int cid = tid + l * 256;
        int r = cid >> 2, c8 = (cid & 3) * 8;
        cpa16(sptr(st + r * 40 + c8), Ab + (size_t)(by + r) * K + k0 + c8);
        int rb = cid >> 4, cb = (cid & 15) * 8;
        cpa16(sptr(st + 5120 + rb * 136 + cb), Bg + (size_t)(k0 + rb) * N + bx + cb);
    }
}

template <int EPI>  // 0: fp32 out  1: fp16 out  2: gelu -> fp16 out
__global__ __launch_bounds__(256, 2) void k_hgemm(
    const __half* __restrict__ Ab, const __half* __restrict__ Bg,
    const float* __restrict__ bias,
    float* __restrict__ Cf, __half* __restrict__ Cb,
    int M, int N, int K) {
    extern __shared__ __half sm[];
    int tid = threadIdx.x;
    int warp = tid >> 5, lane = tid & 31;
    int wm = warp >> 2, wn = warp & 3;
    int by = blockIdx.y * 128, bx = blockIdx.x * 128;

    float acc[4][4][4];
#pragma unroll
    for (int i = 0; i < 4; i++)
#pragma unroll
        for (int j = 0; j < 4; j++)
#pragma unroll
            for (int f = 0; f < 4; f++) acc[i][j][f] = 0.f;

    int nt = K >> 5;
    g_issue(sm, Ab, Bg, 0, K, N, by, bx, tid);
    CP_COMMIT;
    g_issue(sm + GSTG, Ab, Bg, 32, K, N, by, bx, tid);
    CP_COMMIT;

    for (int i = 0; i < nt; i++) {
        if (i + 1 < nt) { CP_WAIT(1); } else { CP_WAIT(0); }
        __syncthreads();
        __half* cur = sm + (i % 3) * GSTG;
        const __half* sA = cur;
        const __half* sB = cur + 5120;
#pragma unroll
        for (int ks = 0; ks < 32; ks += 16) {
            unsigned ah[4][4];
#pragma unroll
            for (int mi = 0; mi < 4; mi++) {
                int row = wm * 64 + mi * 16 + (lane & 15);
                int ce = ks + (lane >> 4) * 8;
                ldsm4(ah[mi], sptr(sA + row * 40 + ce));
            }
#pragma unroll
            for (int ni = 0; ni < 4; ni++) {
                unsigned bf[2];
                int kr = ks + (lane & 15);
                int col = wn * 32 + ni * 8;
                ldsm2t(bf, sptr(sB + kr * 136 + col));
#pragma unroll
                for (int mi = 0; mi < 4; mi++)
                    mma16816h(acc[mi][ni], ah[mi], bf);
            }
        }
        __syncthreads();
        if (i + 2 < nt) {
            g_issue(sm + ((i + 2) % 3) * GSTG, Ab, Bg, (i + 2) * 32, K, N, by, bx, tid);
            CP_COMMIT;
        }
    }

    int r0 = by + wm * 64;
    int c0 = bx + wn * 32;
    int lr = lane >> 2, lc = (lane & 3) * 2;
#pragma unroll
    for (int mi = 0; mi < 4; mi++) {
#pragma unroll
        for (int ni = 0; ni < 4; ni++) {
            int col = c0 + ni * 8 + lc;
            float b0 = bias[col], b1 = bias[col + 1];
            int rA = r0 + mi * 16 + lr, rB = rA + 8;
            float v0 = acc[mi][ni][0] + b0, v1 = acc[mi][ni][1] + b1;
            float v2 = acc[mi][ni][2] + b0, v3 = acc[mi][ni][3] + b1;
            if (EPI == 2) {
                v0 = gelu_exact(v0); v1 = gelu_exact(v1);
                v2 = gelu_exact(v2); v3 = gelu_exact(v3);
            }
            if (EPI == 0) {
                Cf[(size_t)rA * N + col] = v0; Cf[(size_t)rA * N + col + 1] = v1;
                Cf[(size_t)rB * N + col] = v2; Cf[(size_t)rB * N + col + 1] = v3;
            } else {
                Cb[(size_t)rA * N + col]     = __float2half_rn(v0);
                Cb[(size_t)rA * N + col + 1] = __float2half_rn(v1);
                Cb[(size_t)rB * N + col]     = __float2half_rn(v2);
                Cb[(size_t)rB * N + col + 1] = __float2half_rn(v3);
            }
        }
    }
}

// ---------------- fused flash attention (fp16, 2-stage cp.async) ------
// One block: 64 q rows of one (b,h). 128 threads = 4 warps, 16 q rows/warp.
// dyn smem: QB@0 (9216B), stage s @ 9216+s*18432 {K@0, V@9216}, madd @46080
constexpr int FSM_BYTES = 46080 + 8192;   // 54272

__global__ __launch_bounds__(128) void k_flash(
    const __half* __restrict__ q, const __half* __restrict__ k,
    const __half* __restrict__ v, const int* __restrict__ mask,
    __half* __restrict__ o) {
    extern __shared__ __align__(16) char fsm[];
    __half* QB = (__half*)fsm;
    float* madd = (float*)(fsm + 46080);

    int bh = blockIdx.y;
    int b = bh >> 4, h = bh & 15;
    int q0 = blockIdx.x * 64;
    int tid = threadIdx.x, warp = tid >> 5, lane = tid & 31;
    int g = lane >> 2, t = lane & 3;

    const __half* qg = q + ((size_t)(b * Ss + q0)) * Ee + h * Dd;
    const __half* kg = k + ((size_t)(b * Ss)) * Ee + h * Dd;
    const __half* vg = v + ((size_t)(b * Ss)) * Ee + h * Dd;

#pragma unroll
    for (int l = 0; l < 4; l++) {
        int cid = tid + l * 128;
        int r = cid >> 3, c8 = (cid & 7) * 8;
        cpa16(sptr(QB + r * 72 + c8), qg + (size_t)r * Ee + c8);
    }
    CP_COMMIT;
    {
        __half* st = (__half*)(fsm + 9216);
#pragma unroll
        for (int l = 0; l < 4; l++) {
            int cid = tid + l * 128;
            int r = cid >> 3, c8 = (cid & 7) * 8;
            cpa16(sptr(st + r * 72 + c8), kg + (size_t)r * Ee + c8);
            cpa16(sptr(st + 4608 + r * 72 + c8), vg + (size_t)r * Ee + c8);
        }
        CP_COMMIT;
    }

    for (int i = tid; i < Ss; i += 128)
        madd[i] = mask[b * Ss + i] ? 0.f : -1e30f;

    CP_WAIT(1);
    __syncthreads();
    unsigned qf[4][4];
#pragma unroll
    for (int ks = 0; ks < 4; ks++) {
        int row = warp * 16 + (lane & 15);
        int ce = ks * 16 + (lane >> 4) * 8;
        ldsm4(qf[ks], sptr(QB + row * 72 + ce));
    }

    float oacc[8][4];
#pragma unroll
    for (int i = 0; i < 8; i++)
#pragma unroll
        for (int f = 0; f < 4; f++) oacc[i][f] = 0.f;
    float m0 = -INFINITY, m1 = -INFINITY;
    float l0s = 0.f, l1s = 0.f;

    constexpr int NT = Ss / 64;
    for (int ti = 0; ti < NT; ti++) {
        if (ti + 1 < NT) {
            __half* st = (__half*)(fsm + 9216 + ((ti + 1) & 1) * 18432);
            int kt = (ti + 1) * 64;
#pragma unroll
            for (int l = 0; l < 4; l++) {
                int cid = tid + l * 128;
                int r = cid >> 3, c8 = (cid & 7) * 8;
                cpa16(sptr(st + r * 72 + c8), kg + (size_t)(kt + r) * Ee + c8);
                cpa16(sptr(st + 4608 + r * 72 + c8), vg + (size_t)(kt + r) * Ee + c8);
            }
            CP_COMMIT;
            CP_WAIT(1);
        } else {
            CP_WAIT(0);
        }
        __syncthreads();
        const __half* Kt = (const __half*)(fsm + 9216 + (ti & 1) * 18432);
        const __half* Vt = Kt + 4608;
        int kt = ti * 64;

        float sacc[8][4];
#pragma unroll
        for (int i = 0; i < 8; i++)
#pragma unroll
            for (int f = 0; f < 4; f++) sacc[i][f] = 0.f;
#pragma unroll
        for (int ks = 0; ks < 4; ks++) {
#pragma unroll
            for (int ni = 0; ni < 8; ni++) {
                unsigned kb2[2];
                int row = ni * 8 + (lane & 7);
                int ce = ks * 16 + ((lane >> 3) & 1) * 8;
                ldsm2(kb2, sptr(Kt + row * 72 + ce));
                mma16816h(sacc[ni], qf[ks], kb2);
            }
        }

        const float scale = 0.125f;
        float mc0 = -INFINITY, mc1 = -INFINITY;
#pragma unroll
        for (int ni = 0; ni < 8; ni++) {
            int col = kt + ni * 8 + 2 * t;
            float ma = madd[col], mb = madd[col + 1];
            float s0 = sacc[ni][0] * scale + ma;
            float s1 = sacc[ni][1] * scale + mb;
            float s2 = sacc[ni][2] * scale + ma;
            float s3 = sacc[ni][3] * scale + mb;
            sacc[ni][0] = s0; sacc[ni][1] = s1;
            sacc[ni][2] = s2; sacc[ni][3] = s3;
            mc0 = fmaxf(mc0, fmaxf(s0, s1));
            mc1 = fmaxf(mc1, fmaxf(s2, s3));
        }
        mc0 = fmaxf(mc0, __shfl_xor_sync(0xffffffffu, mc0, 1));
        mc0 = fmaxf(mc0, __shfl_xor_sync(0xffffffffu, mc0, 2));
        mc1 = fmaxf(mc1, __shfl_xor_sync(0xffffffffu, mc1, 1));
        mc1 = fmaxf(mc1, __shfl_xor_sync(0xffffffffu, mc1, 2));
        float mn0 = fmaxf(m0, mc0), mn1 = fmaxf(m1, mc1);
        float alpha0 = __expf(m0 - mn0), alpha1 = __expf(m1 - mn1);

        float sum0 = 0.f, sum1 = 0.f;
#pragma unroll
        for (int ni = 0; ni < 8; ni++) {
            float p0 = __expf(sacc[ni][0] - mn0);
            float p1 = __expf(sacc[ni][1] - mn0);
            float p2 = __expf(sacc[ni][2] - mn1);
            float p3 = __expf(sacc[ni][3] - mn1);
            sacc[ni][0] = p0; sacc[ni][1] = p1;
            sacc[ni][2] = p2; sacc[ni][3] = p3;
            sum0 += p0 + p1; sum1 += p2 + p3;
        }
        sum0 += __shfl_xor_sync(0xffffffffu, sum0, 1);
        sum0 += __shfl_xor_sync(0xffffffffu, sum0, 2);
        sum1 += __shfl_xor_sync(0xffffffffu, sum1, 1);
        sum1 += __shfl_xor_sync(0xffffffffu, sum1, 2);
        l0s = l0s * alpha0 + sum0;
        l1s = l1s * alpha1 + sum1;
        m0 = mn0; m1 = mn1;

#pragma unroll
        for (int ni = 0; ni < 8; ni++) {
            oacc[ni][0] *= alpha0; oacc[ni][1] *= alpha0;
            oacc[ni][2] *= alpha1; oacc[ni][3] *= alpha1;
        }

#pragma unroll
        for (int j = 0; j < 4; j++) {
            unsigned pa[4];
            pa[0] = pack2h(__float2half_rn(sacc[2 * j][0]), __float2half_rn(sacc[2 * j][1]));
            pa[1] = pack2h(__float2half_rn(sacc[2 * j][2]), __float2half_rn(sacc[2 * j][3]));
            pa[2] = pack2h(__float2half_rn(sacc[2 * j + 1][0]), __float2half_rn(sacc[2 * j + 1][1]));
            pa[3] = pack2h(__float2half_rn(sacc[2 * j + 1][2]), __float2half_rn(sacc[2 * j + 1][3]));
#pragma unroll
            for (int ni = 0; ni < 8; ni++) {
                unsigned vh2[2];
                int kr = j * 16 + (lane & 15);
                ldsm2t(vh2, sptr(Vt + kr * 72 + ni * 8));
                mma16816h(oacc[ni], pa, vh2);
            }
        }
        __syncthreads();
    }

    float inv0 = 1.0f / l0s, inv1 = 1.0f / l1s;
    int r0 = q0 + warp * 16 + g, r1 = r0 + 8;
#pragma unroll
    for (int ni = 0; ni < 8; ni++) {
        int col = h * Dd + ni * 8 + 2 * t;
        size_t oA = ((size_t)(b * Ss + r0)) * Ee + col;
        size_t oB = ((size_t)(b * Ss + r1)) * Ee + col;
        o[oA]     = __float2half_rn(oacc[ni][0] * inv0);
        o[oA + 1] = __float2half_rn(oacc[ni][1] * inv0);
        o[oB]     = __float2half_rn(oacc[ni][2] * inv1);
        o[oB + 1] = __float2half_rn(oacc[ni][3] * inv1);
    }
}

// ---------------- residual + layernorm -> fp16 ----------------
__global__ void k_ln(const float* __restrict__ wo_out,
                     const float* __restrict__ x,
                     const float* __restrict__ g,
                     const float* __restrict__ be,
                     __half* __restrict__ outb) {
    __shared__ float red[256];
    __shared__ float s_mu, s_rstd;
    int t = blockIdx.x;
    int tid = threadIdx.x;
    const float* pa = wo_out + (size_t)t * Ee;
    const float* px = x + (size_t)t * Ee;
    float loc[4];
    float sum = 0.f;
#pragma unroll
    for (int i = 0; i < 4; i++) {
        int idx = i * 256 + tid;
        float vv = pa[idx] + px[idx];
        loc[i] = vv;
        sum += vv;
    }
    red[tid] = sum; __syncthreads();
    for (int s = 128; s > 0; s >>= 1) {
        if (tid < s) red[tid] += red[tid + s];
        __syncthreads();
    }
    if (tid == 0) s_mu = red[0] * (1.0f / Ee);
    __syncthreads();
    float mu = s_mu;
    float vs = 0.f;
#pragma unroll
    for (int i = 0; i < 4; i++) {
        float d = loc[i] - mu;
        vs += d * d;
    }
    red[tid] = vs; __syncthreads();
    for (int s = 128; s > 0; s >>= 1) {
        if (tid < s) red[tid] += red[tid + s];
        __syncthreads();
    }
    if (tid == 0) s_rstd = rsqrtf(red[0] * (1.0f / Ee) + 1e-5f);
    __syncthreads();
    float rstd = s_rstd;
#pragma unroll
    for (int i = 0; i < 4; i++) {
        int idx = i * 256 + tid;
        float o = (loc[i] - mu) * rstd * g[idx] + be[idx];
        outb[(size_t)t * Ee + idx] = __float2half_rn(o);
    }
}

// ---------------- partial column sums of ff2 ----------------
__global__ void k_pmean(const float* __restrict__ f2, float* __restrict__ part) {
    int e = blockIdx.x * 256 + threadIdx.x;
    int b = blockIdx.y;
    int p = blockIdx.z;
    float s = 0.f;
    int s0 = p * 32;
    for (int i = 0; i < 32; i++)
        s += f2[((size_t)(b * Ss + s0 + i)) * Ee + e];
    part[((size_t)p * Bb + b) * Ee + e] = s;
}

// ---------------- final ----------------
__global__ void k_final(const float* __restrict__ part,
                        const float* __restrict__ Wp,
                        const float* __restrict__ bp,
                        float* __restrict__ out) {
    int w = threadIdx.x >> 5;
    int lane = threadIdx.x & 31;
    if (w >= 12) return;
    int b = w / 3, j = w % 3;
    float acc = 0.f;
    for (int e = lane; e < Ee; e += 32) {
        float s = 0.f;
#pragma unroll
        for (int p = 0; p < 64; p++)
            s += part[((size_t)p * Bb + b) * Ee + e];
        acc += s * Wp[e * 3 + j];
    }
#pragma unroll
    for (int o = 16; o > 0; o >>= 1)
        acc += __shfl_down_sync(0xffffffff, acc, o);
    if (lane == 0) out[b * 3 + j] = acc * (1.0f / Ss) + bp[j];
}

// ---------------- launch ----------------
extern "C" void kernel_launch(void* const* d_in, const int* in_sizes, int n_in,
                              void* d_out, int out_size) {
    const int*   ids  = (const int*)d_in[0];
    const int*   mask = (const int*)d_in[1];
    const float* emb  = (const float*)d_in[2];
    const float* Wq = (const float*)d_in[3],  *bq = (const float*)d_in[4];
    const float* Wk = (const float*)d_in[5],  *bk = (const float*)d_in[6];
    const float* Wv = (const float*)d_in[7],  *bv = (const float*)d_in[8];
    const float* Wo = (const float*)d_in[9],  *bo = (const float*)d_in[10];
    const float* lg = (const float*)d_in[11], *lb = (const float*)d_in[12];
    const float* W1 = (const float*)d_in[13], *b1 = (const float*)d_in[14];
    const float* W2 = (const float*)d_in[15], *b2 = (const float*)d_in[16];
    const float* Wp = (const float*)d_in[17], *bp = (const float*)d_in[18];

    float *x, *wo, *f2, *pt;
    __half *xb, *qb, *kb, *vb, *ab, *hb, *f1b;
    __half *wq, *wk, *wv, *wom, *w1, *w2;
    cudaGetSymbolAddress((void**)&x,   g_x);
    cudaGetSymbolAddress((void**)&xb,  g_xb);
    cudaGetSymbolAddress((void**)&qb,  g_qb);
    cudaGetSymbolAddress((void**)&kb,  g_kb);
    cudaGetSymbolAddress((void**)&vb,  g_vb);
    cudaGetSymbolAddress((void**)&ab,  g_ab);
    cudaGetSymbolAddress((void**)&wo,  g_wo);
    cudaGetSymbolAddress((void**)&hb,  g_hb);
    cudaGetSymbolAddress((void**)&f1b, g_f1b);
    cudaGetSymbolAddress((void**)&f2,  g_f2);
    cudaGetSymbolAddress((void**)&pt,  g_pt);
    cudaGetSymbolAddress((void**)&wq,  g_wq);
    cudaGetSymbolAddress((void**)&wk,  g_wk);
    cudaGetSymbolAddress((void**)&wv,  g_wv);
    cudaGetSymbolAddress((void**)&wom, g_wom);
    cudaGetSymbolAddress((void**)&w1,  g_w1);
    cudaGetSymbolAddress((void**)&w2,  g_w2);

    cudaFuncSetAttribute(k_hgemm<0>, cudaFuncAttributeMaxDynamicSharedMemorySize, GSM_BYTES);
    cudaFuncSetAttribute(k_hgemm<1>, cudaFuncAttributeMaxDynamicSharedMemorySize, GSM_BYTES);
    cudaFuncSetAttribute(k_hgemm<2>, cudaFuncAttributeMaxDynamicSharedMemorySize, GSM_BYTES);
    cudaFuncSetAttribute(k_flash,    cudaFuncAttributeMaxDynamicSharedMemorySize, FSM_BYTES);

    // weight conversions
    k_half<<<(Ee * Ee) / 1024, 256>>>(Wq, wq, Ee * Ee);
    k_half<<<(Ee * Ee) / 1024, 256>>>(Wk, wk, Ee * Ee);
    k_half<<<(Ee * Ee) / 1024, 256>>>(Wv, wv, Ee * Ee);
    k_half<<<(Ee * Ee) / 1024, 256>>>(Wo, wom, Ee * Ee);
    k_half<<<(Ee * Ff) / 1024, 256>>>(W1, w1, Ee * Ff);
    k_half<<<(Ff * Ee) / 1024, 256>>>(W2, w2, Ff * Ee);

    k_embed<<<BS, 256>>>(ids, emb, x, xb);

    k_hgemm<1><<<dim3(Ee / 128, BS / 128), 256, GSM_BYTES>>>(
        xb, wq, bq, nullptr, qb, BS, Ee, Ee);
    k_hgemm<1><<<dim3(Ee / 128, BS / 128), 256, GSM_BYTES>>>(
        xb, wk, bk, nullptr, kb, BS, Ee, Ee);
    k_hgemm<1><<<dim3(Ee / 128, BS / 128), 256, GSM_BYTES>>>(
        xb, wv, bv, nullptr, vb, BS, Ee, Ee);

    k_flash<<<dim3(Ss / 64, BH), 128, FSM_BYTES>>>(qb, kb, vb, mask, ab);

    k_hgemm<0><<<dim3(Ee / 128, BS / 128), 256, GSM_BYTES>>>(
        ab, wom, bo, wo, nullptr, BS, Ee, Ee);
    k_ln<<<BS, 256>>>(wo, x, lg, lb, hb);

    k_hgemm<2><<<dim3(Ff / 128, BS / 128), 256, GSM_BYTES>>>(
        hb, w1, b1, nullptr, f1b, BS, Ff, Ee);
    k_hgemm<0><<<dim3(Ee / 128, BS / 128), 256, GSM_BYTES>>>(
        f1b, w2, b2, f2, nullptr, BS, Ee, Ff);

    k_pmean<<<dim3(Ee / 256, Bb, 64), 256>>>(f2, pt);
    k_final<<<1, 384>>>(pt, Wp, bp, (float*)d_out);
}